// round 1
// baseline (speedup 1.0000x reference)
#include <cuda_runtime.h>

// ======================= static scratch (no cudaMalloc allowed) =======================
__device__ float g_x0[2097152];     // [4*1024, 512] set-0 activations
__device__ float g_x1[2097152];
__device__ float g_q [2097152];
__device__ float g_k [2097152];
__device__ float g_v [2097152];
__device__ float g_prob[33554432];  // [4,8,1024,1024] attention scores/probs
__device__ float g_mrg[2097152];    // merged heads
__device__ float g_cat[4194304];    // [4096, 1024] concat(x, msg)
__device__ float g_z  [4194304];    // [4096, 1024] MLP hidden
__device__ float g_d0 [2097152];
__device__ float g_d1 [2097152];
__device__ float g_m0 [2097152];
__device__ float g_m1 [2097152];
__device__ float g_coup[4202500];   // [4,1025,1025]
__device__ float g_u [4100];
__device__ float g_vv[4100];

#define NORM_C  (-7.6246189861593985f)   // -log(2048)
#define BIN_MU  (-0.6931471805599453f)   // log(1024)-log(2048)

// ======================= generic NT GEMM: C = alpha*A(M,K) * B(N,K)^T + bias =========
// 128x128x8 tile, 256 threads, 8x8 microtile. Requires M%128==0, N%128==0, K%8==0.
// grid.z batching: off = (z/zmod)*S1 + (z%zmod)*S2 per operand.
__global__ __launch_bounds__(256) void gemm_nt(
    const float* __restrict__ A, int lda, long aS1, long aS2,
    const float* __restrict__ B, int ldb, long bS1, long bS2,
    const float* __restrict__ bias,
    float* __restrict__ C, int ldc, long cS1, long cS2,
    int K, int zmod, float alpha)
{
    int z = blockIdx.z;
    int z1 = z / zmod, z2 = z - z1 * zmod;
    A += z1 * aS1 + z2 * aS2;
    B += z1 * bS1 + z2 * bS2;
    C += z1 * cS1 + z2 * cS2;
    __shared__ float As[8][128];
    __shared__ float Bs[8][128];
    const int tid  = threadIdx.x;
    const int bm   = blockIdx.y * 128, bn = blockIdx.x * 128;
    const int lrow = tid >> 1, lcol = (tid & 1) * 4;
    const int tr   = (tid >> 4) * 8, tc = (tid & 15) * 8;
    const float* Ap = A + (long)(bm + lrow) * lda + lcol;
    const float* Bp = B + (long)(bn + lrow) * ldb + lcol;
    float acc[8][8] = {};
    for (int k0 = 0; k0 < K; k0 += 8) {
        float4 a4 = *(const float4*)(Ap + k0);
        float4 b4 = *(const float4*)(Bp + k0);
        As[lcol+0][lrow] = a4.x; As[lcol+1][lrow] = a4.y;
        As[lcol+2][lrow] = a4.z; As[lcol+3][lrow] = a4.w;
        Bs[lcol+0][lrow] = b4.x; Bs[lcol+1][lrow] = b4.y;
        Bs[lcol+2][lrow] = b4.z; Bs[lcol+3][lrow] = b4.w;
        __syncthreads();
        #pragma unroll
        for (int k = 0; k < 8; k++) {
            float ar[8], br[8];
            #pragma unroll
            for (int i = 0; i < 8; i++) ar[i] = As[k][tr + i];
            #pragma unroll
            for (int j = 0; j < 8; j++) br[j] = Bs[k][tc + j];
            #pragma unroll
            for (int i = 0; i < 8; i++)
                #pragma unroll
                for (int j = 0; j < 8; j++)
                    acc[i][j] = fmaf(ar[i], br[j], acc[i][j]);
        }
        __syncthreads();
    }
    #pragma unroll
    for (int i = 0; i < 8; i++) {
        long m = bm + tr + i;
        #pragma unroll
        for (int j = 0; j < 8; j++) {
            int n = bn + tc + j;
            float val = alpha * acc[i][j];
            if (bias) val += bias[n];
            C[m * ldc + n] = val;
        }
    }
}

// ======================= P @ V (NN), per (b,h): [1024x1024]x[1024x64] ================
// Writes merged heads with channel = hd*8 + h (torch's dim-major head merge).
__global__ __launch_bounds__(256) void gemm_pv()
{
    int z = blockIdx.z, b = z >> 3, h = z & 7;
    const float* A  = g_prob + (long)z * 1048576;          // [1024,1024]
    const float* Bv = g_v + (long)b * 524288 + h * 64;     // rows m, 64 cols
    float* C = g_mrg + (long)b * 524288 + h;               // col stride 8
    __shared__ float As[8][128];
    __shared__ float Bs[8][64];
    const int tid  = threadIdx.x;
    const int bm   = blockIdx.y * 128;
    const int lrow = tid >> 1, lcol = (tid & 1) * 4;
    const int brow = tid >> 5, bcol = (tid & 31) * 2;
    const int tr   = (tid >> 4) * 8, tc = (tid & 15) * 4;
    float acc[8][4] = {};
    for (int k0 = 0; k0 < 1024; k0 += 8) {
        float4 a4 = *(const float4*)(A + (long)(bm + lrow) * 1024 + k0 + lcol);
        float2 b2 = *(const float2*)(Bv + (long)(k0 + brow) * 512 + bcol);
        As[lcol+0][lrow]=a4.x; As[lcol+1][lrow]=a4.y;
        As[lcol+2][lrow]=a4.z; As[lcol+3][lrow]=a4.w;
        Bs[brow][bcol] = b2.x; Bs[brow][bcol+1] = b2.y;
        __syncthreads();
        #pragma unroll
        for (int k = 0; k < 8; k++) {
            float ar[8], br[4];
            #pragma unroll
            for (int i = 0; i < 8; i++) ar[i] = As[k][tr+i];
            #pragma unroll
            for (int j = 0; j < 4; j++) br[j] = Bs[k][tc+j];
            #pragma unroll
            for (int i = 0; i < 8; i++)
                #pragma unroll
                for (int j = 0; j < 4; j++)
                    acc[i][j] = fmaf(ar[i], br[j], acc[i][j]);
        }
        __syncthreads();
    }
    #pragma unroll
    for (int i = 0; i < 8; i++)
        #pragma unroll
        for (int j = 0; j < 4; j++)
            C[(long)(bm + tr + i) * 512 + (tc + j) * 8] = acc[i][j];
}

// ======================= softmax over rows of [*, 1024], scale 1/8 ===================
__global__ __launch_bounds__(256) void softmax_rows(float* __restrict__ P)
{
    float* row = P + (long)blockIdx.x * 1024;
    const int t = threadIdx.x;
    float v[4];
    float mx = -1e30f;
    #pragma unroll
    for (int i = 0; i < 4; i++) { v[i] = row[t + 256*i] * 0.125f; mx = fmaxf(mx, v[i]); }
    __shared__ float sh[256];
    sh[t] = mx; __syncthreads();
    for (int o = 128; o > 0; o >>= 1) { if (t < o) sh[t] = fmaxf(sh[t], sh[t+o]); __syncthreads(); }
    mx = sh[0]; __syncthreads();
    float s = 0.f;
    #pragma unroll
    for (int i = 0; i < 4; i++) { v[i] = __expf(v[i] - mx); s += v[i]; }
    sh[t] = s; __syncthreads();
    for (int o = 128; o > 0; o >>= 1) { if (t < o) sh[t] += sh[t+o]; __syncthreads(); }
    float inv = 1.f / sh[0];
    #pragma unroll
    for (int i = 0; i < 4; i++) row[t + 256*i] = v[i] * inv;
}

// ======================= InstanceNorm1d(affine=False) + ReLU, in place ===============
// Z: [4 batches x 1024 rows, 1024 channels]; normalize each (b, channel) over rows.
__global__ __launch_bounds__(256) void instnorm_relu(float* __restrict__ Z)
{
    int b = blockIdx.x >> 5;           // 32 channel-groups per batch
    int g = blockIdx.x & 31;
    int lane = threadIdx.x & 31, w = threadIdx.x >> 5;
    int c = g * 32 + lane;
    float* base = Z + (long)b * 1048576 + c;
    float s = 0.f;
    for (int n = w; n < 1024; n += 8) s += base[(long)n * 1024];
    __shared__ float sh[8][32];
    sh[w][lane] = s; __syncthreads();
    if (w == 0) { float a = 0; for (int i = 0; i < 8; i++) a += sh[i][lane]; sh[0][lane] = a * (1.f/1024.f); }
    __syncthreads();
    float mean = sh[0][lane];
    __syncthreads();
    float s2 = 0.f;
    for (int n = w; n < 1024; n += 8) { float d = base[(long)n * 1024] - mean; s2 += d * d; }
    sh[w][lane] = s2; __syncthreads();
    if (w == 0) { float a = 0; for (int i = 0; i < 8; i++) a += sh[i][lane];
                  sh[0][lane] = rsqrtf(a * (1.f/1024.f) + 1e-5f); }
    __syncthreads();
    float inv = sh[0][lane];
    for (int n = w; n < 1024; n += 8) {
        long off = (long)n * 1024;
        float x = (base[off] - mean) * inv;
        base[off] = fmaxf(x, 0.f);
    }
}

// ======================= elementwise helpers =========================================
__global__ void copy4(float4* __restrict__ dst, const float4* __restrict__ src)
{
    long t = (long)blockIdx.x * 256 + threadIdx.x;
    dst[t] = src[t];
}
__global__ void add4(float4* __restrict__ x, const float4* __restrict__ d)
{
    long t = (long)blockIdx.x * 256 + threadIdx.x;
    float4 a = x[t], b = d[t];
    a.x += b.x; a.y += b.y; a.z += b.z; a.w += b.w;
    x[t] = a;
}
__global__ void copy_to_cat(const float4* __restrict__ x)   // x [4096x512] -> cat[:, :512]
{
    long t = (long)blockIdx.x * 256 + threadIdx.x;          // 524288 float4s
    long r = t >> 7, c = t & 127;
    ((float4*)g_cat)[r * 256 + c] = x[t];
}

// ======================= Sinkhorn ====================================================
__global__ void sink_init(const float* __restrict__ bin)
{
    float a = *bin;
    int t = blockIdx.x * 256 + threadIdx.x;
    if (t < 4100) g_u[t] = 0.f;
    if (t >= 4100 && t < 8200) g_vv[t - 4100] = 0.f;
    if (t < 8196) {
        int b = t / 2049, r = t - b * 2049;
        float* cb = g_coup + (long)b * 1050625;
        if (r < 1024) cb[(long)r * 1025 + 1024] = a;      // right bin column
        else          cb[(long)1024 * 1025 + (r - 1024)] = a;  // bottom bin row (+corner)
    }
}

__global__ __launch_bounds__(256) void sink_u()   // u = log_mu - lse_j(C + v)
{
    int r = blockIdx.x;                 // 0..4099
    int b = r / 1025, i = r - b * 1025;
    const float* row = g_coup + (long)b * 1050625 + (long)i * 1025;
    const float* vb = g_vv + b * 1025;
    int t = threadIdx.x;
    float m = -1e30f, s = 0.f;
    for (int j = t; j < 1025; j += 256) {
        float x = row[j] + vb[j];
        if (x > m) { s = s * __expf(m - x) + 1.f; m = x; }
        else         s += __expf(x - m);
    }
    __shared__ float sm[256], ss[256];
    sm[t] = m; ss[t] = s; __syncthreads();
    for (int o = 128; o > 0; o >>= 1) {
        if (t < o) {
            float m2 = sm[t+o], s2 = ss[t+o];
            float M = fmaxf(sm[t], m2);
            ss[t] = ss[t] * __expf(sm[t] - M) + s2 * __expf(m2 - M);
            sm[t] = M;
        }
        __syncthreads();
    }
    if (t == 0) {
        float lse = logf(ss[0]) + sm[0];
        g_u[r] = ((i < 1024) ? NORM_C : BIN_MU) - lse;
    }
}

__global__ __launch_bounds__(256) void sink_v()   // v = log_nu - lse_i(C + u)
{
    int b = blockIdx.y;
    int lane = threadIdx.x & 31, ty = threadIdx.x >> 5;   // 8 row-slices
    int j = blockIdx.x * 32 + lane;
    const float* base = g_coup + (long)b * 1050625;
    const float* ub = g_u + b * 1025;
    float m = -1e30f, s = 0.f;
    if (j < 1025) {
        for (int i = ty; i < 1025; i += 8) {
            float x = base[(long)i * 1025 + j] + ub[i];
            if (x > m) { s = s * __expf(m - x) + 1.f; m = x; }
            else         s += __expf(x - m);
        }
    }
    __shared__ float sm[8][32], ss[8][32];
    sm[ty][lane] = m; ss[ty][lane] = s; __syncthreads();
    if (ty == 0 && j < 1025) {
        float M = m, S = s;
        #pragma unroll
        for (int w = 1; w < 8; w++) {
            float m2 = sm[w][lane], s2 = ss[w][lane];
            float Mn = fmaxf(M, m2);
            S = S * __expf(M - Mn) + s2 * __expf(m2 - Mn);
            M = Mn;
        }
        float lse = logf(S) + M;
        g_vv[b * 1025 + j] = ((j < 1024) ? NORM_C : BIN_MU) - lse;
    }
}

__global__ void final_out(float* __restrict__ out)
{
    long t = (long)blockIdx.x * 256 + threadIdx.x;
    if (t >= 4202500L) return;
    int b = (int)(t / 1050625);
    int rem = (int)(t - (long)b * 1050625);
    int i = rem / 1025, j = rem - i * 1025;
    out[t] = g_coup[t] + g_u[b * 1025 + i] + g_vv[b * 1025 + j] - NORM_C;
}

// ======================= driver ======================================================
extern "C" void kernel_launch(void* const* d_in, const int* in_sizes, int n_in,
                              void* d_out, int out_size)
{
    (void)in_sizes; (void)n_in; (void)out_size;
    const float* Wq = (const float*)d_in[2];  const float* bq = (const float*)d_in[3];
    const float* Wk = (const float*)d_in[4];  const float* bk = (const float*)d_in[5];
    const float* Wv = (const float*)d_in[6];  const float* bv = (const float*)d_in[7];
    const float* Wm = (const float*)d_in[8];  const float* bm = (const float*)d_in[9];
    const float* W1 = (const float*)d_in[10]; const float* b1 = (const float*)d_in[11];
    const float* W2 = (const float*)d_in[12]; const float* b2 = (const float*)d_in[13];
    const float* Wf = (const float*)d_in[14]; const float* bf = (const float*)d_in[15];
    const float* bin = (const float*)d_in[16];

    float *px0, *px1, *pq, *pk, *pv, *pprob, *pmrg, *pcat, *pz, *pd0, *pd1, *pm0, *pm1, *pcoup;
    cudaGetSymbolAddress((void**)&px0,  g_x0);
    cudaGetSymbolAddress((void**)&px1,  g_x1);
    cudaGetSymbolAddress((void**)&pq,   g_q);
    cudaGetSymbolAddress((void**)&pk,   g_k);
    cudaGetSymbolAddress((void**)&pv,   g_v);
    cudaGetSymbolAddress((void**)&pprob,g_prob);
    cudaGetSymbolAddress((void**)&pmrg, g_mrg);
    cudaGetSymbolAddress((void**)&pcat, g_cat);
    cudaGetSymbolAddress((void**)&pz,   g_z);
    cudaGetSymbolAddress((void**)&pd0,  g_d0);
    cudaGetSymbolAddress((void**)&pd1,  g_d1);
    cudaGetSymbolAddress((void**)&pm0,  g_m0);
    cudaGetSymbolAddress((void**)&pm1,  g_m1);
    cudaGetSymbolAddress((void**)&pcoup,g_coup);

    // init activations from inputs (already [B,N,D] row-major = [4096,512])
    copy4<<<2048, 256>>>((float4*)px0, (const float4*)d_in[0]);
    copy4<<<2048, 256>>>((float4*)px1, (const float4*)d_in[1]);

    const dim3 gP(4, 32, 1);     // N=512 GEMMs over M=4096
    for (int i = 0; i < 12; i++) {
        const bool cross = (i & 1);
        const float* Wqi = Wq + (long)i * 262144;  const float* bqi = bq + i * 512;
        const float* Wki = Wk + (long)i * 262144;  const float* bki = bk + i * 512;
        const float* Wvi = Wv + (long)i * 262144;  const float* bvi = bv + i * 512;
        const float* Wmi = Wm + (long)i * 262144;  const float* bmi = bm + i * 512;
        const float* W1i = W1 + (long)i * 1048576; const float* b1i = b1 + i * 1024;
        const float* W2i = W2 + (long)i * 524288;  const float* b2i = b2 + i * 512;

        for (int tset = 0; tset < 2; tset++) {
            float* x   = tset ? px1 : px0;
            float* src = cross ? (tset ? px0 : px1) : x;
            float* dd  = tset ? pd1 : pd0;

            gemm_nt<<<gP, 256>>>(x,   512, 0, 0, Wqi, 512, 0, 0, bqi, pq, 512, 0, 0, 512, 1, 1.f);
            gemm_nt<<<gP, 256>>>(src, 512, 0, 0, Wki, 512, 0, 0, bki, pk, 512, 0, 0, 512, 1, 1.f);
            gemm_nt<<<gP, 256>>>(src, 512, 0, 0, Wvi, 512, 0, 0, bvi, pv, 512, 0, 0, 512, 1, 1.f);
            // scores: per (b,h)  q_bh @ k_bh^T   (scale folded into softmax)
            gemm_nt<<<dim3(8, 8, 32), 256>>>(pq, 512, 524288, 64,
                                             pk, 512, 524288, 64, nullptr,
                                             pprob, 1024, 8388608, 1048576, 64, 8, 1.f);
            softmax_rows<<<32768, 256>>>(pprob);
            gemm_pv<<<dim3(1, 8, 32), 256>>>();
            copy_to_cat<<<2048, 256>>>((const float4*)x);
            // message = merged @ Wm^T + bm  -> cat[:, 512:]
            gemm_nt<<<gP, 256>>>(pmrg, 512, 0, 0, Wmi, 512, 0, 0, bmi,
                                 pcat + 512, 1024, 0, 0, 512, 1, 1.f);
            gemm_nt<<<dim3(8, 32, 1), 256>>>(pcat, 1024, 0, 0, W1i, 1024, 0, 0, b1i,
                                             pz, 1024, 0, 0, 1024, 1, 1.f);
            instnorm_relu<<<128, 256>>>(pz);
            gemm_nt<<<gP, 256>>>(pz, 1024, 0, 0, W2i, 1024, 0, 0, b2i,
                                 dd, 512, 0, 0, 1024, 1, 1.f);
        }
        add4<<<2048, 256>>>((float4*)px0, (const float4*)pd0);
        add4<<<2048, 256>>>((float4*)px1, (const float4*)pd1);
    }

    // final projection + score matrix (written straight into couplings rows/cols < 1024)
    gemm_nt<<<gP, 256>>>(px0, 512, 0, 0, Wf, 512, 0, 0, bf, pm0, 512, 0, 0, 512, 1, 1.f);
    gemm_nt<<<gP, 256>>>(px1, 512, 0, 0, Wf, 512, 0, 0, bf, pm1, 512, 0, 0, 512, 1, 1.f);
    gemm_nt<<<dim3(8, 8, 4), 256>>>(pm0, 512, 524288, 0,
                                    pm1, 512, 524288, 0, nullptr,
                                    pcoup, 1025, 1050625, 0, 512, 1,
                                    0.04419417382415922f);   // 1/sqrt(512)

    sink_init<<<33, 256>>>(bin);
    for (int it = 0; it < 100; it++) {
        sink_u<<<4100, 256>>>();
        sink_v<<<dim3(33, 4), 256>>>();
    }
    final_out<<<16417, 256>>>((float*)d_out);
}

// round 2
// speedup vs baseline: 2.7994x; 2.7994x over previous
#include <cuda_runtime.h>

// ======================= static scratch =======================
__device__ float g_act[8388608];     // [2 pairs][2 tsets][4096? ->] ping-pong activation pairs
__device__ float g_q [4194304];      // [2 tsets][4096, 512]
__device__ float g_k [4194304];
__device__ float g_vt[4194304];      // [2 tsets][4, 512, 1024]  (per-batch transposed V)
__device__ float g_prob[67108864];   // [2 tsets][4,8,1024,1024]
__device__ float g_mrg[4194304];     // [2 tsets][4096, 512] head-major merged
__device__ float g_cat[8388608];     // [2 tsets][4096, 1024]
__device__ float g_z  [8388608];     // [2 tsets][4096, 1024]
__device__ float g_mfin[4194304];    // [2 sets][4096, 512]
__device__ float g_coup[4202500];    // [4,1025,1025]
__device__ float g_u [4100];
__device__ float g_vv[4100];
__device__ float g_wpack[9437184];   // [12][1536][512]  (Wq|Wk|Wv rows)
__device__ float g_bpack[18432];     // [12][1536]
__device__ float g_wmp[3145728];     // [12][512][512]   Wm with permuted cols

#define NORM_C  (-7.6246189861593985f)   // -log(2048)
#define BIN_MU  (-0.6931471805599453f)   // log(1024)-log(2048)
#define LDS 36
#define GEMM_SMEM (4*128*LDS*4)          // 73728 B : 2 stages x (A+B) 128x36
#define PV_SMEM   ((2*128*LDS + 2*64*LDS)*4)

// ======================= tensor-core primitives =======================
__device__ __forceinline__ unsigned f2tf(float x) {
    unsigned u; asm("cvt.rna.tf32.f32 %0, %1;" : "=r"(u) : "f"(x)); return u;
}
__device__ __forceinline__ void mma8(float* d, const unsigned* a, const unsigned* b) {
    asm volatile(
        "mma.sync.aligned.m16n8k8.row.col.f32.tf32.tf32.f32 "
        "{%0,%1,%2,%3}, {%4,%5,%6,%7}, {%8,%9}, {%0,%1,%2,%3};\n"
        : "+f"(d[0]), "+f"(d[1]), "+f"(d[2]), "+f"(d[3])
        : "r"(a[0]), "r"(a[1]), "r"(a[2]), "r"(a[3]), "r"(b[0]), "r"(b[1]));
}
__device__ __forceinline__ void cpa16(float* s, const float* g) {
    unsigned sa = (unsigned)__cvta_generic_to_shared(s);
    asm volatile("cp.async.ca.shared.global [%0], [%1], 16;\n" :: "r"(sa), "l"(g));
}

// ======================= TF32 NT GEMM: C = alpha*A(M,K)*B(N,K)^T (+bias)(+resid) ====
// 128x128x32 tile, 256 thr, 8 warps (2M x 4N), warp tile 64x32, m16n8k8 tf32.
// qkv_mode: epilogue scatters cols [0,512)->g_q, [512,1024)->g_k, [1024,1536)->g_vt^T.
__global__ __launch_bounds__(256, 2) void gemm_tc(
    const float* __restrict__ A, int lda, long aS1, long aS2,
    const float* __restrict__ B, int ldb, long bS1, long bS2,
    const float* __restrict__ bias,
    float* __restrict__ C, int ldc, long cS1, long cS2,
    const float* __restrict__ resid, long rS1,
    int K, int zmod, float alpha, int qkv_mode)
{
    extern __shared__ float smem[];
    float* As = smem;                 // [2][128*LDS]
    float* Bs = smem + 2 * 128 * LDS;
    const int z = blockIdx.z, z1 = z / zmod, z2 = z - z1 * zmod;
    A += z1 * aS1 + z2 * aS2;
    B += z1 * bS1 + z2 * bS2;
    C += z1 * cS1 + z2 * cS2;
    if (resid) resid += z1 * rS1;
    const int tid = threadIdx.x;
    const int bm = blockIdx.y * 128, bn = blockIdx.x * 128;
    const int KT = K >> 5;

    auto issue = [&](int kt, int st) {
        const float* Ag = A + (long)bm * lda + kt * 32;
        float* as = As + st * 128 * LDS;
        #pragma unroll
        for (int i = 0; i < 4; i++) {
            int idx = tid + i * 256, r = idx >> 3, c = (idx & 7) * 4;
            cpa16(as + r * LDS + c, Ag + (long)r * lda + c);
        }
        const float* Bg = B + (long)bn * ldb + kt * 32;
        float* bs = Bs + st * 128 * LDS;
        #pragma unroll
        for (int i = 0; i < 4; i++) {
            int idx = tid + i * 256, r = idx >> 3, c = (idx & 7) * 4;
            cpa16(bs + r * LDS + c, Bg + (long)r * ldb + c);
        }
        asm volatile("cp.async.commit_group;\n");
    };

    float acc[4][4][4] = {};
    const int wid = tid >> 5, lane = tid & 31;
    const int wm = wid & 1, wn = wid >> 1, g = lane >> 2, q = lane & 3;

    issue(0, 0);
    for (int kt = 0; kt < KT; kt++) {
        int st = kt & 1;
        if (kt + 1 < KT) { issue(kt + 1, st ^ 1); asm volatile("cp.async.wait_group 1;\n"); }
        else             { asm volatile("cp.async.wait_group 0;\n"); }
        __syncthreads();
        const float* as = As + st * 128 * LDS;
        const float* bs = Bs + st * 128 * LDS;
        #pragma unroll
        for (int k8 = 0; k8 < 4; k8++) {
            unsigned af[4][4], bf[4][2];
            #pragma unroll
            for (int mt = 0; mt < 4; mt++) {
                const float* p = as + (wm * 64 + mt * 16 + g) * LDS + k8 * 8 + q;
                af[mt][0] = f2tf(p[0]);       af[mt][1] = f2tf(p[8 * LDS]);
                af[mt][2] = f2tf(p[4]);       af[mt][3] = f2tf(p[8 * LDS + 4]);
            }
            #pragma unroll
            for (int nt = 0; nt < 4; nt++) {
                const float* p = bs + (wn * 32 + nt * 8 + g) * LDS + k8 * 8 + q;
                bf[nt][0] = f2tf(p[0]);       bf[nt][1] = f2tf(p[4]);
            }
            #pragma unroll
            for (int mt = 0; mt < 4; mt++)
                #pragma unroll
                for (int nt = 0; nt < 4; nt++) mma8(acc[mt][nt], af[mt], bf[nt]);
        }
        __syncthreads();
    }

    const long zoff = (long)blockIdx.z * 2097152;   // tset offset for qkv mode
    #pragma unroll
    for (int mt = 0; mt < 4; mt++)
        #pragma unroll
        for (int nt = 0; nt < 4; nt++) {
            int r0 = bm + wm * 64 + mt * 16 + g;
            int c0 = bn + wn * 32 + nt * 8 + q * 2;
            #pragma unroll
            for (int i2 = 0; i2 < 2; i2++) {
                int r = r0 + i2 * 8;
                #pragma unroll
                for (int j2 = 0; j2 < 2; j2++) {
                    int c = c0 + j2;
                    float v = alpha * acc[mt][nt][i2 * 2 + j2];
                    if (bias) v += bias[c];
                    if (qkv_mode) {
                        if (c < 512)       g_q[zoff + (long)r * 512 + c] = v;
                        else if (c < 1024) g_k[zoff + (long)r * 512 + (c - 512)] = v;
                        else g_vt[zoff + (long)(r >> 10) * 524288 +
                                  (long)(c - 1024) * 1024 + (r & 1023)] = v;
                    } else {
                        if (resid) v += resid[(long)r * ldc + c];
                        C[(long)r * ldc + c] = v;
                    }
                }
            }
        }
}

// ======================= P @ V^T tensor GEMM: [1024x1024] x [64,1024]^T =============
// grid: (8 bm, 1, 32 bh). P, VT, Cm bases passed per tset launch.
__global__ __launch_bounds__(256, 2) void gemm_pv_tc(
    const float* __restrict__ P, const float* __restrict__ VT, float* __restrict__ Cm)
{
    extern __shared__ float smem[];
    float* As = smem;                 // [2][128*LDS]
    float* Bs = smem + 2 * 128 * LDS; // [2][64*LDS]
    const int z = blockIdx.z, b = z >> 3, h = z & 7;
    const float* A = P + (long)z * 1048576;
    const float* B = VT + (long)b * 524288 + (long)(h * 64) * 1024;
    float* C = Cm + (long)b * 524288 + h * 64;
    const int tid = threadIdx.x;
    const int bm = blockIdx.x * 128;

    auto issue = [&](int kt, int st) {
        const float* Ag = A + (long)bm * 1024 + kt * 32;
        float* as = As + st * 128 * LDS;
        #pragma unroll
        for (int i = 0; i < 4; i++) {
            int idx = tid + i * 256, r = idx >> 3, c = (idx & 7) * 4;
            cpa16(as + r * LDS + c, Ag + (long)r * 1024 + c);
        }
        const float* Bg = B + kt * 32;
        float* bs = Bs + st * 64 * LDS;
        #pragma unroll
        for (int i = 0; i < 2; i++) {
            int idx = tid + i * 256, r = idx >> 3, c = (idx & 7) * 4;
            cpa16(bs + r * LDS + c, Bg + (long)r * 1024 + c);
        }
        asm volatile("cp.async.commit_group;\n");
    };

    float acc[2][4][4] = {};
    const int wid = tid >> 5, lane = tid & 31;
    const int wm = wid & 3, wn = wid >> 2, g = lane >> 2, q = lane & 3;

    issue(0, 0);
    for (int kt = 0; kt < 32; kt++) {
        int st = kt & 1;
        if (kt + 1 < 32) { issue(kt + 1, st ^ 1); asm volatile("cp.async.wait_group 1;\n"); }
        else             { asm volatile("cp.async.wait_group 0;\n"); }
        __syncthreads();
        const float* as = As + st * 128 * LDS;
        const float* bs = Bs + st * 64 * LDS;
        #pragma unroll
        for (int k8 = 0; k8 < 4; k8++) {
            unsigned af[2][4], bf[4][2];
            #pragma unroll
            for (int mt = 0; mt < 2; mt++) {
                const float* p = as + (wm * 32 + mt * 16 + g) * LDS + k8 * 8 + q;
                af[mt][0] = f2tf(p[0]);  af[mt][1] = f2tf(p[8 * LDS]);
                af[mt][2] = f2tf(p[4]);  af[mt][3] = f2tf(p[8 * LDS + 4]);
            }
            #pragma unroll
            for (int nt = 0; nt < 4; nt++) {
                const float* p = bs + (wn * 32 + nt * 8 + g) * LDS + k8 * 8 + q;
                bf[nt][0] = f2tf(p[0]);  bf[nt][1] = f2tf(p[4]);
            }
            #pragma unroll
            for (int mt = 0; mt < 2; mt++)
                #pragma unroll
                for (int nt = 0; nt < 4; nt++) mma8(acc[mt][nt], af[mt], bf[nt]);
        }
        __syncthreads();
    }
    #pragma unroll
    for (int mt = 0; mt < 2; mt++)
        #pragma unroll
        for (int nt = 0; nt < 4; nt++) {
            int r0 = bm + wm * 32 + mt * 16 + g;
            int c0 = wn * 32 + nt * 8 + q * 2;
            #pragma unroll
            for (int i2 = 0; i2 < 2; i2++)
                #pragma unroll
                for (int j2 = 0; j2 < 2; j2++)
                    C[(long)(r0 + i2 * 8) * 512 + c0 + j2] = acc[mt][nt][i2 * 2 + j2];
        }
}

// ======================= weight pack / permute (once per launch) =====================
__global__ void pack_w(const float* __restrict__ Wq, const float* __restrict__ Wk,
                       const float* __restrict__ Wv, const float* __restrict__ bq,
                       const float* __restrict__ bk, const float* __restrict__ bv,
                       const float* __restrict__ Wm)
{
    long t = (long)blockIdx.x * 256 + threadIdx.x;
    if (t < 9437184) {
        long i = t / 786432; long rem = t - i * 786432;
        int row = (int)(rem >> 9), d = (int)(rem & 511);
        const float* src = row < 512 ? Wq : (row < 1024 ? Wk : Wv);
        g_wpack[t] = src[i * 262144 + (long)(row & 511) * 512 + d];
    }
    if (t < 18432) {
        long i = t / 1536; int row = (int)(t - i * 1536);
        const float* sb = row < 512 ? bq : (row < 1024 ? bk : bv);
        g_bpack[t] = sb[i * 512 + (row & 511)];
    }
    if (t < 3145728) {
        long i = t >> 18; long rem = t & 262143;
        int o = (int)(rem >> 9), c = (int)(rem & 511);
        g_wmp[t] = Wm[i * 262144 + (long)o * 512 + (c & 63) * 8 + (c >> 6)];
    }
}

// ======================= softmax over rows of [*, 1024], scale 1/8 ===================
__global__ __launch_bounds__(256) void softmax_rows(float* __restrict__ P)
{
    float* row = P + (long)blockIdx.x * 1024;
    const int t = threadIdx.x;
    float v[4];
    float mx = -1e30f;
    #pragma unroll
    for (int i = 0; i < 4; i++) { v[i] = row[t + 256*i] * 0.125f; mx = fmaxf(mx, v[i]); }
    __shared__ float sh[256];
    sh[t] = mx; __syncthreads();
    for (int o = 128; o > 0; o >>= 1) { if (t < o) sh[t] = fmaxf(sh[t], sh[t+o]); __syncthreads(); }
    mx = sh[0]; __syncthreads();
    float s = 0.f;
    #pragma unroll
    for (int i = 0; i < 4; i++) { v[i] = __expf(v[i] - mx); s += v[i]; }
    sh[t] = s; __syncthreads();
    for (int o = 128; o > 0; o >>= 1) { if (t < o) sh[t] += sh[t+o]; __syncthreads(); }
    float inv = 1.f / sh[0];
    #pragma unroll
    for (int i = 0; i < 4; i++) row[t + 256*i] = v[i] * inv;
}

// ======================= InstanceNorm1d + ReLU over g_z (both tsets) =================
__global__ __launch_bounds__(256) void instnorm_relu()
{
    int bb = blockIdx.x >> 5;          // 0..7 = tset*4+b
    int gch = blockIdx.x & 31;
    int lane = threadIdx.x & 31, w = threadIdx.x >> 5;
    int c = gch * 32 + lane;
    float* base = g_z + (long)bb * 1048576 + c;
    float s = 0.f;
    for (int n = w; n < 1024; n += 8) s += base[(long)n * 1024];
    __shared__ float sh[8][32];
    sh[w][lane] = s; __syncthreads();
    if (w == 0) { float a = 0; for (int i = 0; i < 8; i++) a += sh[i][lane]; sh[0][lane] = a * (1.f/1024.f); }
    __syncthreads();
    float mean = sh[0][lane];
    __syncthreads();
    float s2 = 0.f;
    for (int n = w; n < 1024; n += 8) { float d = base[(long)n * 1024] - mean; s2 += d * d; }
    sh[w][lane] = s2; __syncthreads();
    if (w == 0) { float a = 0; for (int i = 0; i < 8; i++) a += sh[i][lane];
                  sh[0][lane] = rsqrtf(a * (1.f/1024.f) + 1e-5f); }
    __syncthreads();
    float inv = sh[0][lane];
    for (int n = w; n < 1024; n += 8) {
        long off = (long)n * 1024;
        base[off] = fmaxf((base[off] - mean) * inv, 0.f);
    }
}

// ======================= elementwise helpers =========================================
__global__ void copy4(float4* __restrict__ dst, const float4* __restrict__ src)
{
    long t = (long)blockIdx.x * 256 + threadIdx.x;
    dst[t] = src[t];
}
__global__ void copy_to_cat(const float4* __restrict__ x)   // x = cur pair base
{
    long t = (long)blockIdx.x * 256 + threadIdx.x;          // 1048576 float4s
    long ts = t >> 19, rem = t & 524287;
    long r = rem >> 7, c = rem & 127;
    ((float4*)g_cat)[ts * 1048576 + r * 256 + c] = x[ts * 524288 + rem];
}

// ======================= Sinkhorn ====================================================
__global__ void sink_init(const float* __restrict__ bin)
{
    float a = *bin;
    int t = blockIdx.x * 256 + threadIdx.x;
    if (t < 4100) g_u[t] = 0.f;
    if (t >= 4100 && t < 8200) g_vv[t - 4100] = 0.f;
    if (t < 8196) {
        int b = t / 2049, r = t - b * 2049;
        float* cb = g_coup + (long)b * 1050625;
        if (r < 1024) cb[(long)r * 1025 + 1024] = a;
        else          cb[(long)1024 * 1025 + (r - 1024)] = a;
    }
}

__global__ __launch_bounds__(256) void sink_u()
{
    int r = blockIdx.x;
    int b = r / 1025, i = r - b * 1025;
    const float* row = g_coup + (long)b * 1050625 + (long)i * 1025;
    const float* vb = g_vv + b * 1025;
    int t = threadIdx.x;
    float m = -1e30f, s = 0.f;
    for (int j = t; j < 1025; j += 256) {
        float x = row[j] + vb[j];
        if (x > m) { s = s * __expf(m - x) + 1.f; m = x; }
        else         s += __expf(x - m);
    }
    __shared__ float sm[256], ss[256];
    sm[t] = m; ss[t] = s; __syncthreads();
    for (int o = 128; o > 0; o >>= 1) {
        if (t < o) {
            float m2 = sm[t+o], s2 = ss[t+o];
            float M = fmaxf(sm[t], m2);
            ss[t] = ss[t] * __expf(sm[t] - M) + s2 * __expf(m2 - M);
            sm[t] = M;
        }
        __syncthreads();
    }
    if (t == 0) {
        float lse = logf(ss[0]) + sm[0];
        g_u[r] = ((i < 1024) ? NORM_C : BIN_MU) - lse;
    }
}

__global__ __launch_bounds__(256) void sink_v()
{
    int b = blockIdx.y;
    int lane = threadIdx.x & 31, ty = threadIdx.x >> 5;
    int j = blockIdx.x * 32 + lane;
    const float* base = g_coup + (long)b * 1050625;
    const float* ub = g_u + b * 1025;
    float m = -1e30f, s = 0.f;
    if (j < 1025) {
        for (int i = ty; i < 1025; i += 8) {
            float x = base[(long)i * 1025 + j] + ub[i];
            if (x > m) { s = s * __expf(m - x) + 1.f; m = x; }
            else         s += __expf(x - m);
        }
    }
    __shared__ float sm[8][32], ss[8][32];
    sm[ty][lane] = m; ss[ty][lane] = s; __syncthreads();
    if (ty == 0 && j < 1025) {
        float M = m, S = s;
        #pragma unroll
        for (int w = 1; w < 8; w++) {
            float m2 = sm[w][lane], s2 = ss[w][lane];
            float Mn = fmaxf(M, m2);
            S = S * __expf(M - Mn) + s2 * __expf(m2 - Mn);
            M = Mn;
        }
        g_vv[b * 1025 + j] = ((j < 1024) ? NORM_C : BIN_MU) - (logf(S) + M);
    }
}

__global__ void final_out(float* __restrict__ out)
{
    long t = (long)blockIdx.x * 256 + threadIdx.x;
    if (t >= 4202500L) return;
    int b = (int)(t / 1050625);
    int rem = (int)(t - (long)b * 1050625);
    int i = rem / 1025, j = rem - i * 1025;
    out[t] = g_coup[t] + g_u[b * 1025 + i] + g_vv[b * 1025 + j] - NORM_C;
}

// ======================= driver ======================================================
extern "C" void kernel_launch(void* const* d_in, const int* in_sizes, int n_in,
                              void* d_out, int out_size)
{
    (void)in_sizes; (void)n_in; (void)out_size;
    const float* Wq = (const float*)d_in[2];  const float* bq = (const float*)d_in[3];
    const float* Wk = (const float*)d_in[4];  const float* bk = (const float*)d_in[5];
    const float* Wv = (const float*)d_in[6];  const float* bv = (const float*)d_in[7];
    const float* Wm = (const float*)d_in[8];  const float* bm = (const float*)d_in[9];
    const float* W1 = (const float*)d_in[10]; const float* b1 = (const float*)d_in[11];
    const float* W2 = (const float*)d_in[12]; const float* b2 = (const float*)d_in[13];
    const float* Wf = (const float*)d_in[14]; const float* bf = (const float*)d_in[15];
    const float* bin = (const float*)d_in[16];

    cudaFuncSetAttribute(gemm_tc,    cudaFuncAttributeMaxDynamicSharedMemorySize, GEMM_SMEM);
    cudaFuncSetAttribute(gemm_pv_tc, cudaFuncAttributeMaxDynamicSharedMemorySize, PV_SMEM);

    float *pact, *pq, *pk, *pvt, *pprob, *pmrg, *pcat, *pz, *pmfin, *pcoup, *pwpack, *pbpack, *pwmp;
    cudaGetSymbolAddress((void**)&pact,  g_act);
    cudaGetSymbolAddress((void**)&pq,    g_q);
    cudaGetSymbolAddress((void**)&pk,    g_k);
    cudaGetSymbolAddress((void**)&pvt,   g_vt);
    cudaGetSymbolAddress((void**)&pprob, g_prob);
    cudaGetSymbolAddress((void**)&pmrg,  g_mrg);
    cudaGetSymbolAddress((void**)&pcat,  g_cat);
    cudaGetSymbolAddress((void**)&pz,    g_z);
    cudaGetSymbolAddress((void**)&pmfin, g_mfin);
    cudaGetSymbolAddress((void**)&pcoup, g_coup);
    cudaGetSymbolAddress((void**)&pwpack,g_wpack);
    cudaGetSymbolAddress((void**)&pbpack,g_bpack);
    cudaGetSymbolAddress((void**)&pwmp,  g_wmp);

    pack_w<<<36864, 256>>>(Wq, Wk, Wv, bq, bk, bv, Wm);

    float* cur = pact;                 // [tset][4096,512] pair
    float* nxt = pact + 4194304;
    copy4<<<2048, 256>>>((float4*)cur,             (const float4*)d_in[0]);
    copy4<<<2048, 256>>>((float4*)(cur + 2097152), (const float4*)d_in[1]);

    for (int i = 0; i < 12; i++) {
        const bool cross = (i & 1);
        // fused QKV for both tsets (z=2): A=cur pair, B=packed weights
        gemm_tc<<<dim3(12, 32, 2), 256, GEMM_SMEM>>>(
            cur, 512, 2097152, 0, pwpack + (long)i * 786432, 512, 0, 0,
            pbpack + i * 1536, nullptr, 0, 0, 0, nullptr, 0, 512, 1, 1.f, 1);
        // scores + softmax + PV, per tset (cross swaps K/V source)
        for (int ts = 0; ts < 2; ts++) {
            int os = cross ? (1 - ts) : ts;
            gemm_tc<<<dim3(8, 8, 32), 256, GEMM_SMEM>>>(
                pq + (long)ts * 2097152, 512, 524288, 64,
                pk + (long)os * 2097152, 512, 524288, 64, nullptr,
                pprob + (long)ts * 33554432, 1024, 8388608, 1048576,
                nullptr, 0, 64, 8, 1.f, 0);
        }
        softmax_rows<<<65536, 256>>>(pprob);
        for (int ts = 0; ts < 2; ts++) {
            int os = cross ? (1 - ts) : ts;
            gemm_pv_tc<<<dim3(8, 1, 32), 256, PV_SMEM>>>(
                pprob + (long)ts * 33554432, pvt + (long)os * 2097152,
                pmrg + (long)ts * 2097152);
        }
        copy_to_cat<<<4096, 256>>>((const float4*)cur);
        // message -> cat[:,512:1024], both tsets
        gemm_tc<<<dim3(4, 32, 2), 256, GEMM_SMEM>>>(
            pmrg, 512, 2097152, 0, pwmp + (long)i * 262144, 512, 0, 0,
            bm + i * 512, pcat + 512, 1024, 4194304, 0, nullptr, 0, 512, 1, 1.f, 0);
        // MLP1
        gemm_tc<<<dim3(8, 32, 2), 256, GEMM_SMEM>>>(
            pcat, 1024, 4194304, 0, W1 + (long)i * 1048576, 1024, 0, 0,
            b1 + i * 1024, pz, 1024, 4194304, 0, nullptr, 0, 1024, 1, 1.f, 0);
        instnorm_relu<<<256, 256>>>();
        // MLP2 with fused residual: nxt = cur + z @ W2^T + b2
        gemm_tc<<<dim3(4, 32, 2), 256, GEMM_SMEM>>>(
            pz, 1024, 4194304, 0, W2 + (long)i * 524288, 1024, 0, 0,
            b2 + i * 512, nxt, 512, 2097152, 0, cur, 2097152, 1024, 1, 1.f, 0);
        float* tmp = cur; cur = nxt; nxt = tmp;
    }

    // final projection (both sets) + score matrix into couplings
    gemm_tc<<<dim3(4, 32, 2), 256, GEMM_SMEM>>>(
        cur, 512, 2097152, 0, Wf, 512, 0, 0, bf,
        pmfin, 512, 2097152, 0, nullptr, 0, 512, 1, 1.f, 0);
    gemm_tc<<<dim3(8, 8, 4), 256, GEMM_SMEM>>>(
        pmfin, 512, 524288, 0, pmfin + 2097152, 512, 524288, 0, nullptr,
        pcoup, 1025, 1050625, 0, nullptr, 0, 512, 1, 0.04419417382415922f, 0);

    sink_init<<<33, 256>>>(bin);
    for (int it = 0; it < 100; it++) {
        sink_u<<<4100, 256>>>();
        sink_v<<<dim3(33, 4), 256>>>();
    }
    final_out<<<16417, 256>>>((float*)d_out);
}

// round 3
// speedup vs baseline: 3.5724x; 1.2762x over previous
#include <cuda_runtime.h>

// ======================= static scratch =======================
__device__ float g_act[8388608];     // 2 ping-pong [tset][4096,512] fp32 residual stream
__device__ float g_q [4194304];      // [2 tsets][4096, 512] tf32-quantized
__device__ float g_k [4194304];
__device__ float g_v [4194304];
__device__ float g_mrg[4194304];     // [2 tsets][4096, 512] head-major merged (tf32q)
__device__ float g_cat[8388608];     // [2 tsets][4096, 1024] (tf32q)
__device__ float g_z  [8388608];     // [2 tsets][4096, 1024] fp32 from MLP1, tf32q after IN
__device__ float g_mfin[4194304];    // [2 sets][4096, 512] (tf32q)
__device__ float g_coup[4202500];    // [4,1025,1025]
__device__ float g_u [4100];
__device__ float g_vv[4100];
__device__ float g_wpack[9437184];   // [12][1536][512]  Wq|Wk|Wv (tf32q)
__device__ float g_bpack[18432];     // [12][1536]
__device__ float g_wmp[3145728];     // [12][512][512]   Wm cols permuted (tf32q)
__device__ float g_W1q[12582912];    // [12][1024][1024] (tf32q)
__device__ float g_W2q[6291456];     // [12][512][1024]  (tf32q)
__device__ float g_Wfq[262144];      // [512][512]       (tf32q)

#define NORM_C  (-7.6246189861593985f)   // -log(2048)
#define BIN_MU  (-0.6931471805599453f)   // log(1024)-log(2048)
#define LDS 36
#define GEMM_SMEM (4*128*LDS*4)
#define QPAD 68
#define KPAD 68
#define VPAD 72
#define FLASH_SMEM ((128*QPAD + 64*KPAD + 64*VPAD)*4)

// ======================= tensor-core primitives =======================
__device__ __forceinline__ unsigned f2tf(float x) {
    unsigned u; asm("cvt.rna.tf32.f32 %0, %1;" : "=r"(u) : "f"(x)); return u;
}
__device__ __forceinline__ float tfq(float x) { return __uint_as_float(f2tf(x)); }
__device__ __forceinline__ void mma8(float* d, const unsigned* a, const unsigned* b) {
    asm volatile(
        "mma.sync.aligned.m16n8k8.row.col.f32.tf32.tf32.f32 "
        "{%0,%1,%2,%3}, {%4,%5,%6,%7}, {%8,%9}, {%0,%1,%2,%3};\n"
        : "+f"(d[0]), "+f"(d[1]), "+f"(d[2]), "+f"(d[3])
        : "r"(a[0]), "r"(a[1]), "r"(a[2]), "r"(a[3]), "r"(b[0]), "r"(b[1]));
}
__device__ __forceinline__ void cpa16(float* s, const float* g) {
    unsigned sa = (unsigned)__cvta_generic_to_shared(s);
    asm volatile("cp.async.ca.shared.global [%0], [%1], 16;\n" :: "r"(sa), "l"(g));
}

// ======================= TF32 NT GEMM ================================================
// C = alpha*A(M,K)*B(N,K)^T (+bias)(+resid). QA: cvt A operand at read (A is fp32).
// B must be pre-quantized. qkv_mode scatters cols into g_q/g_k/g_v quantized.
template <int QA>
__global__ __launch_bounds__(256, 2) void gemm_tc(
    const float* __restrict__ A, int lda, long aS1, long aS2,
    const float* __restrict__ B, int ldb, long bS1, long bS2,
    const float* __restrict__ bias,
    float* __restrict__ C, int ldc, long cS1, long cS2,
    const float* __restrict__ resid, long rS1,
    int K, int zmod, float alpha, int qkv_mode, int quantO)
{
    extern __shared__ float smem[];
    float* As = smem;
    float* Bs = smem + 2 * 128 * LDS;
    const int z = blockIdx.z, z1 = z / zmod, z2 = z - z1 * zmod;
    A += z1 * aS1 + z2 * aS2;
    B += z1 * bS1 + z2 * bS2;
    C += z1 * cS1 + z2 * cS2;
    if (resid) resid += z1 * rS1;
    const int tid = threadIdx.x;
    const int bm = blockIdx.y * 128, bn = blockIdx.x * 128;
    const int KT = K >> 5;

    auto issue = [&](int kt, int st) {
        const float* Ag = A + (long)bm * lda + kt * 32;
        float* as = As + st * 128 * LDS;
        #pragma unroll
        for (int i = 0; i < 4; i++) {
            int idx = tid + i * 256, r = idx >> 3, c = (idx & 7) * 4;
            cpa16(as + r * LDS + c, Ag + (long)r * lda + c);
        }
        const float* Bg = B + (long)bn * ldb + kt * 32;
        float* bs = Bs + st * 128 * LDS;
        #pragma unroll
        for (int i = 0; i < 4; i++) {
            int idx = tid + i * 256, r = idx >> 3, c = (idx & 7) * 4;
            cpa16(bs + r * LDS + c, Bg + (long)r * ldb + c);
        }
        asm volatile("cp.async.commit_group;\n");
    };

    float acc[4][4][4] = {};
    const int wid = tid >> 5, lane = tid & 31;
    const int wm = wid & 1, wn = wid >> 1, g = lane >> 2, q = lane & 3;

    issue(0, 0);
    for (int kt = 0; kt < KT; kt++) {
        int st = kt & 1;
        if (kt + 1 < KT) { issue(kt + 1, st ^ 1); asm volatile("cp.async.wait_group 1;\n"); }
        else             { asm volatile("cp.async.wait_group 0;\n"); }
        __syncthreads();
        const float* as = As + st * 128 * LDS;
        const float* bs = Bs + st * 128 * LDS;
        #pragma unroll
        for (int k8 = 0; k8 < 4; k8++) {
            unsigned af[4][4], bf[4][2];
            #pragma unroll
            for (int mt = 0; mt < 4; mt++) {
                const float* p = as + (wm * 64 + mt * 16 + g) * LDS + k8 * 8 + q;
                if (QA) {
                    af[mt][0] = f2tf(p[0]);       af[mt][1] = f2tf(p[8 * LDS]);
                    af[mt][2] = f2tf(p[4]);       af[mt][3] = f2tf(p[8 * LDS + 4]);
                } else {
                    af[mt][0] = __float_as_uint(p[0]);
                    af[mt][1] = __float_as_uint(p[8 * LDS]);
                    af[mt][2] = __float_as_uint(p[4]);
                    af[mt][3] = __float_as_uint(p[8 * LDS + 4]);
                }
            }
            #pragma unroll
            for (int nt = 0; nt < 4; nt++) {
                const float* p = bs + (wn * 32 + nt * 8 + g) * LDS + k8 * 8 + q;
                bf[nt][0] = __float_as_uint(p[0]);
                bf[nt][1] = __float_as_uint(p[4]);
            }
            #pragma unroll
            for (int mt = 0; mt < 4; mt++)
                #pragma unroll
                for (int nt = 0; nt < 4; nt++) mma8(acc[mt][nt], af[mt], bf[nt]);
        }
        __syncthreads();
    }

    const long zoff = (long)blockIdx.z * 2097152;
    #pragma unroll
    for (int mt = 0; mt < 4; mt++)
        #pragma unroll
        for (int nt = 0; nt < 4; nt++) {
            int r0 = bm + wm * 64 + mt * 16 + g;
            int c0 = bn + wn * 32 + nt * 8 + q * 2;
            #pragma unroll
            for (int i2 = 0; i2 < 2; i2++) {
                int r = r0 + i2 * 8;
                #pragma unroll
                for (int j2 = 0; j2 < 2; j2++) {
                    int c = c0 + j2;
                    float v = alpha * acc[mt][nt][i2 * 2 + j2];
                    if (bias) v += bias[c];
                    if (qkv_mode) {
                        float vq = tfq(v);
                        if (c < 512)       g_q[zoff + (long)r * 512 + c] = vq;
                        else if (c < 1024) g_k[zoff + (long)r * 512 + (c - 512)] = vq;
                        else               g_v[zoff + (long)r * 512 + (c - 1024)] = vq;
                    } else {
                        if (resid) v += resid[(long)r * ldc + c];
                        if (quantO) v = tfq(v);
                        C[(long)r * ldc + c] = v;
                    }
                }
            }
        }
}

// ======================= fused flash attention =======================================
// Per block: 128 query rows of one (b,h,ts). KV tiles of 64. Writes merged heads
// (head-major col = h*64+d) tf32-quantized into g_mrg. Q/K/V pre-quantized.
__global__ __launch_bounds__(256, 2) void flash_attn(int cross)
{
    extern __shared__ float smem[];
    float* Qs = smem;                  // [128][QPAD]
    float* Ks = smem + 128 * QPAD;     // [64][KPAD]
    float* Vs = Ks + 64 * KPAD;        // [64][VPAD]
    const int ts = blockIdx.z;
    const int os = cross ? (1 - ts) : ts;
    const int bh = blockIdx.y, b = bh >> 3, h = bh & 7;
    const int m0 = blockIdx.x * 128;
    const int tid = threadIdx.x, wid = tid >> 5, lane = tid & 31;
    const int g = lane >> 2, q = lane & 3;

    const float* Qg = g_q + (long)ts * 2097152 + (long)(b * 1024 + m0) * 512 + h * 64;
    const float* Kg = g_k + (long)os * 2097152 + (long)(b * 1024) * 512 + h * 64;
    const float* Vg = g_v + (long)os * 2097152 + (long)(b * 1024) * 512 + h * 64;

    #pragma unroll
    for (int i = 0; i < 8; i++) {
        int idx = tid + i * 256, r = idx >> 4, c = (idx & 15) * 4;
        cpa16(Qs + r * QPAD + c, Qg + (long)r * 512 + c);
    }
    asm volatile("cp.async.commit_group;\n");

    auto loadKV = [&](int t) {
        #pragma unroll
        for (int i = 0; i < 4; i++) {
            int idx = tid + i * 256, r = idx >> 4, c = (idx & 15) * 4;
            cpa16(Ks + r * KPAD + c, Kg + (long)(t * 64 + r) * 512 + c);
        }
        #pragma unroll
        for (int i = 0; i < 4; i++) {
            int idx = tid + i * 256, r = idx >> 4, c = (idx & 15) * 4;
            cpa16(Vs + r * VPAD + c, Vg + (long)(t * 64 + r) * 512 + c);
        }
        asm volatile("cp.async.commit_group;\n");
    };
    loadKV(0);

    const int wr = wid * 16;
    float mp0 = -1e30f, mp1 = -1e30f, l0 = 0.f, l1 = 0.f;
    float o[8][4] = {};

    for (int t = 0; t < 16; t++) {
        asm volatile("cp.async.wait_group 0;\n");
        __syncthreads();
        float s[8][4] = {};
        #pragma unroll
        for (int j = 0; j < 8; j++) {
            unsigned aq[4];
            const float* p = Qs + (wr + g) * QPAD + j * 8 + q;
            aq[0] = __float_as_uint(p[0]);
            aq[1] = __float_as_uint(p[8 * QPAD]);
            aq[2] = __float_as_uint(p[4]);
            aq[3] = __float_as_uint(p[8 * QPAD + 4]);
            #pragma unroll
            for (int nt = 0; nt < 8; nt++) {
                unsigned bk[2];
                const float* kp = Ks + (nt * 8 + g) * KPAD + j * 8 + q;
                bk[0] = __float_as_uint(kp[0]);
                bk[1] = __float_as_uint(kp[4]);
                mma8(s[nt], aq, bk);
            }
        }
        // scale + online softmax
        float lm0 = -1e30f, lm1 = -1e30f;
        #pragma unroll
        for (int nt = 0; nt < 8; nt++) {
            #pragma unroll
            for (int e = 0; e < 4; e++) s[nt][e] *= 0.125f;
            lm0 = fmaxf(lm0, fmaxf(s[nt][0], s[nt][1]));
            lm1 = fmaxf(lm1, fmaxf(s[nt][2], s[nt][3]));
        }
        lm0 = fmaxf(lm0, __shfl_xor_sync(0xffffffff, lm0, 1));
        lm0 = fmaxf(lm0, __shfl_xor_sync(0xffffffff, lm0, 2));
        lm1 = fmaxf(lm1, __shfl_xor_sync(0xffffffff, lm1, 1));
        lm1 = fmaxf(lm1, __shfl_xor_sync(0xffffffff, lm1, 2));
        float mn0 = fmaxf(mp0, lm0), mn1 = fmaxf(mp1, lm1);
        float a0 = __expf(mp0 - mn0), a1 = __expf(mp1 - mn1);
        float ps0 = 0.f, ps1 = 0.f;
        #pragma unroll
        for (int nt = 0; nt < 8; nt++) {
            s[nt][0] = __expf(s[nt][0] - mn0);
            s[nt][1] = __expf(s[nt][1] - mn0);
            s[nt][2] = __expf(s[nt][2] - mn1);
            s[nt][3] = __expf(s[nt][3] - mn1);
            ps0 += s[nt][0] + s[nt][1];
            ps1 += s[nt][2] + s[nt][3];
        }
        ps0 += __shfl_xor_sync(0xffffffff, ps0, 1);
        ps0 += __shfl_xor_sync(0xffffffff, ps0, 2);
        ps1 += __shfl_xor_sync(0xffffffff, ps1, 1);
        ps1 += __shfl_xor_sync(0xffffffff, ps1, 2);
        l0 = l0 * a0 + ps0;  l1 = l1 * a1 + ps1;
        mp0 = mn0;  mp1 = mn1;
        #pragma unroll
        for (int tt = 0; tt < 8; tt++) {
            o[tt][0] *= a0; o[tt][1] *= a0; o[tt][2] *= a1; o[tt][3] *= a1;
        }
        // PV: A-frag from s[j] via quad shuffles
        const int srcA = (lane & ~3) | (q >> 1);
        const int srcB = srcA + 2;
        const bool odd = q & 1;
        #pragma unroll
        for (int j = 0; j < 8; j++) {
            float v00 = __shfl_sync(0xffffffff, s[j][0], srcA);
            float v01 = __shfl_sync(0xffffffff, s[j][1], srcA);
            float v10 = __shfl_sync(0xffffffff, s[j][2], srcA);
            float v11 = __shfl_sync(0xffffffff, s[j][3], srcA);
            float w00 = __shfl_sync(0xffffffff, s[j][0], srcB);
            float w01 = __shfl_sync(0xffffffff, s[j][1], srcB);
            float w10 = __shfl_sync(0xffffffff, s[j][2], srcB);
            float w11 = __shfl_sync(0xffffffff, s[j][3], srcB);
            unsigned ap[4];
            ap[0] = f2tf(odd ? v01 : v00);
            ap[1] = f2tf(odd ? v11 : v10);
            ap[2] = f2tf(odd ? w01 : w00);
            ap[3] = f2tf(odd ? w11 : w10);
            #pragma unroll
            for (int tt = 0; tt < 8; tt++) {
                unsigned bv[2];
                bv[0] = __float_as_uint(Vs[(j * 8 + q) * VPAD + tt * 8 + g]);
                bv[1] = __float_as_uint(Vs[(j * 8 + q + 4) * VPAD + tt * 8 + g]);
                mma8(o[tt], ap, bv);
            }
        }
        __syncthreads();
        if (t < 15) loadKV(t + 1);
    }

    float inv0 = 1.f / l0, inv1 = 1.f / l1;
    float* Og = g_mrg + (long)ts * 2097152 + (long)(b * 1024 + m0 + wr) * 512 + h * 64;
    #pragma unroll
    for (int tt = 0; tt < 8; tt++) {
        int c = tt * 8 + q * 2;
        Og[(long)g * 512 + c]           = tfq(o[tt][0] * inv0);
        Og[(long)g * 512 + c + 1]       = tfq(o[tt][1] * inv0);
        Og[(long)(g + 8) * 512 + c]     = tfq(o[tt][2] * inv1);
        Og[(long)(g + 8) * 512 + c + 1] = tfq(o[tt][3] * inv1);
    }
}

// ======================= weight pack / quantize (once per launch) ====================
__global__ void pack_w(const float* __restrict__ Wq, const float* __restrict__ Wk,
                       const float* __restrict__ Wv, const float* __restrict__ bq,
                       const float* __restrict__ bk, const float* __restrict__ bv,
                       const float* __restrict__ Wm, const float* __restrict__ W1,
                       const float* __restrict__ W2, const float* __restrict__ Wf)
{
    long t = (long)blockIdx.x * 256 + threadIdx.x;
    if (t < 9437184) {
        long i = t / 786432; long rem = t - i * 786432;
        int row = (int)(rem >> 9), d = (int)(rem & 511);
        const float* src = row < 512 ? Wq : (row < 1024 ? Wk : Wv);
        g_wpack[t] = tfq(src[i * 262144 + (long)(row & 511) * 512 + d]);
    }
    if (t < 18432) {
        long i = t / 1536; int row = (int)(t - i * 1536);
        const float* sb = row < 512 ? bq : (row < 1024 ? bk : bv);
        g_bpack[t] = sb[i * 512 + (row & 511)];
    }
    if (t < 3145728) {
        long i = t >> 18; long rem = t & 262143;
        int o = (int)(rem >> 9), c = (int)(rem & 511);
        g_wmp[t] = tfq(Wm[i * 262144 + (long)o * 512 + (c & 63) * 8 + (c >> 6)]);
    }
    if (t < 12582912) g_W1q[t] = tfq(W1[t]);
    if (t < 6291456)  g_W2q[t] = tfq(W2[t]);
    if (t < 262144)   g_Wfq[t] = tfq(Wf[t]);
}

// ======================= InstanceNorm1d + ReLU (writes tf32q) ========================
__global__ __launch_bounds__(256) void instnorm_relu()
{
    int bb = blockIdx.x >> 5;
    int gch = blockIdx.x & 31;
    int lane = threadIdx.x & 31, w = threadIdx.x >> 5;
    int c = gch * 32 + lane;
    float* base = g_z + (long)bb * 1048576 + c;
    float s = 0.f;
    for (int n = w; n < 1024; n += 8) s += base[(long)n * 1024];
    __shared__ float sh[8][32];
    sh[w][lane] = s; __syncthreads();
    if (w == 0) { float a = 0; for (int i = 0; i < 8; i++) a += sh[i][lane]; sh[0][lane] = a * (1.f/1024.f); }
    __syncthreads();
    float mean = sh[0][lane];
    __syncthreads();
    float s2 = 0.f;
    for (int n = w; n < 1024; n += 8) { float d = base[(long)n * 1024] - mean; s2 += d * d; }
    sh[w][lane] = s2; __syncthreads();
    if (w == 0) { float a = 0; for (int i = 0; i < 8; i++) a += sh[i][lane];
                  sh[0][lane] = rsqrtf(a * (1.f/1024.f) + 1e-5f); }
    __syncthreads();
    float inv = sh[0][lane];
    for (int n = w; n < 1024; n += 8) {
        long off = (long)n * 1024;
        base[off] = tfq(fmaxf((base[off] - mean) * inv, 0.f));
    }
}

// ======================= elementwise helpers =========================================
__global__ void copy4(float4* __restrict__ dst, const float4* __restrict__ src)
{
    long t = (long)blockIdx.x * 256 + threadIdx.x;
    dst[t] = src[t];
}
__global__ void copy_to_cat(const float4* __restrict__ x)   // quantize x into cat[:, :512]
{
    long t = (long)blockIdx.x * 256 + threadIdx.x;          // 1048576 float4s
    long ts = t >> 19, rem = t & 524287;
    long r = rem >> 7, c = rem & 127;
    float4 v = x[ts * 524288 + rem];
    v.x = tfq(v.x); v.y = tfq(v.y); v.z = tfq(v.z); v.w = tfq(v.w);
    ((float4*)g_cat)[ts * 1048576 + r * 256 + c] = v;
}

// ======================= Sinkhorn ====================================================
__global__ void sink_init(const float* __restrict__ bin)
{
    float a = *bin;
    int t = blockIdx.x * 256 + threadIdx.x;
    if (t < 4100) g_u[t] = 0.f;
    if (t >= 4100 && t < 8200) g_vv[t - 4100] = 0.f;
    if (t < 8196) {
        int b = t / 2049, r = t - b * 2049;
        float* cb = g_coup + (long)b * 1050625;
        if (r < 1024) cb[(long)r * 1025 + 1024] = a;
        else          cb[(long)1024 * 1025 + (r - 1024)] = a;
    }
}

__global__ __launch_bounds__(256) void sink_u()
{
    int r = blockIdx.x;
    int b = r / 1025, i = r - b * 1025;
    const float* row = g_coup + (long)b * 1050625 + (long)i * 1025;
    const float* vb = g_vv + b * 1025;
    int t = threadIdx.x;
    float m = -1e30f, s = 0.f;
    for (int j = t; j < 1025; j += 256) {
        float x = row[j] + vb[j];
        if (x > m) { s = s * __expf(m - x) + 1.f; m = x; }
        else         s += __expf(x - m);
    }
    __shared__ float sm[256], ss[256];
    sm[t] = m; ss[t] = s; __syncthreads();
    for (int o = 128; o > 0; o >>= 1) {
        if (t < o) {
            float m2 = sm[t+o], s2 = ss[t+o];
            float M = fmaxf(sm[t], m2);
            ss[t] = ss[t] * __expf(sm[t] - M) + s2 * __expf(m2 - M);
            sm[t] = M;
        }
        __syncthreads();
    }
    if (t == 0) {
        float lse = logf(ss[0]) + sm[0];
        g_u[r] = ((i < 1024) ? NORM_C : BIN_MU) - lse;
    }
}

__global__ __launch_bounds__(256) void sink_v()
{
    int b = blockIdx.y;
    int lane = threadIdx.x & 31, ty = threadIdx.x >> 5;
    int j = blockIdx.x * 32 + lane;
    const float* base = g_coup + (long)b * 1050625;
    const float* ub = g_u + b * 1025;
    float m = -1e30f, s = 0.f;
    if (j < 1025) {
        for (int i = ty; i < 1025; i += 8) {
            float x = base[(long)i * 1025 + j] + ub[i];
            if (x > m) { s = s * __expf(m - x) + 1.f; m = x; }
            else         s += __expf(x - m);
        }
    }
    __shared__ float sm[8][32], ss[8][32];
    sm[ty][lane] = m; ss[ty][lane] = s; __syncthreads();
    if (ty == 0 && j < 1025) {
        float M = m, S = s;
        #pragma unroll
        for (int w = 1; w < 8; w++) {
            float m2 = sm[w][lane], s2 = ss[w][lane];
            float Mn = fmaxf(M, m2);
            S = S * __expf(M - Mn) + s2 * __expf(m2 - Mn);
            M = Mn;
        }
        g_vv[b * 1025 + j] = ((j < 1024) ? NORM_C : BIN_MU) - (logf(S) + M);
    }
}

__global__ void final_out(float* __restrict__ out)
{
    long t = (long)blockIdx.x * 256 + threadIdx.x;
    if (t >= 4202500L) return;
    int b = (int)(t / 1050625);
    int rem = (int)(t - (long)b * 1050625);
    int i = rem / 1025, j = rem - i * 1025;
    out[t] = g_coup[t] + g_u[b * 1025 + i] + g_vv[b * 1025 + j] - NORM_C;
}

// ======================= driver ======================================================
extern "C" void kernel_launch(void* const* d_in, const int* in_sizes, int n_in,
                              void* d_out, int out_size)
{
    (void)in_sizes; (void)n_in; (void)out_size;
    const float* Wq = (const float*)d_in[2];  const float* bq = (const float*)d_in[3];
    const float* Wk = (const float*)d_in[4];  const float* bk = (const float*)d_in[5];
    const float* Wv = (const float*)d_in[6];  const float* bv = (const float*)d_in[7];
    const float* Wm = (const float*)d_in[8];  const float* bm = (const float*)d_in[9];
    const float* W1 = (const float*)d_in[10]; const float* b1 = (const float*)d_in[11];
    const float* W2 = (const float*)d_in[12]; const float* b2 = (const float*)d_in[13];
    const float* Wf = (const float*)d_in[14]; const float* bf = (const float*)d_in[15];
    const float* bin = (const float*)d_in[16];

    cudaFuncSetAttribute(gemm_tc<0>, cudaFuncAttributeMaxDynamicSharedMemorySize, GEMM_SMEM);
    cudaFuncSetAttribute(gemm_tc<1>, cudaFuncAttributeMaxDynamicSharedMemorySize, GEMM_SMEM);
    cudaFuncSetAttribute(flash_attn, cudaFuncAttributeMaxDynamicSharedMemorySize, FLASH_SMEM);

    float *pact, *pcat, *pz, *pmfin, *pcoup, *pwpack, *pbpack, *pwmp, *pW1q, *pW2q, *pWfq, *pmrg;
    cudaGetSymbolAddress((void**)&pact,  g_act);
    cudaGetSymbolAddress((void**)&pcat,  g_cat);
    cudaGetSymbolAddress((void**)&pz,    g_z);
    cudaGetSymbolAddress((void**)&pmfin, g_mfin);
    cudaGetSymbolAddress((void**)&pcoup, g_coup);
    cudaGetSymbolAddress((void**)&pwpack,g_wpack);
    cudaGetSymbolAddress((void**)&pbpack,g_bpack);
    cudaGetSymbolAddress((void**)&pwmp,  g_wmp);
    cudaGetSymbolAddress((void**)&pW1q,  g_W1q);
    cudaGetSymbolAddress((void**)&pW2q,  g_W2q);
    cudaGetSymbolAddress((void**)&pWfq,  g_Wfq);
    cudaGetSymbolAddress((void**)&pmrg,  g_mrg);

    pack_w<<<49152, 256>>>(Wq, Wk, Wv, bq, bk, bv, Wm, W1, W2, Wf);

    float* cur = pact;
    float* nxt = pact + 4194304;
    copy4<<<2048, 256>>>((float4*)cur,             (const float4*)d_in[0]);
    copy4<<<2048, 256>>>((float4*)(cur + 2097152), (const float4*)d_in[1]);

    for (int i = 0; i < 12; i++) {
        const int cross = (i & 1);
        // fused QKV (A = fp32 residual stream -> QA=1), scatter-quantize into q/k/v
        gemm_tc<1><<<dim3(12, 32, 2), 256, GEMM_SMEM>>>(
            cur, 512, 2097152, 0, pwpack + (long)i * 786432, 512, 0, 0,
            pbpack + i * 1536, nullptr, 0, 0, 0, nullptr, 0, 512, 1, 1.f, 1, 0);
        // fused attention (scores + softmax + PV), writes merged heads
        flash_attn<<<dim3(8, 32, 2), 256, FLASH_SMEM>>>(cross);
        copy_to_cat<<<4096, 256>>>((const float4*)cur);
        // message -> cat[:,512:1024]
        gemm_tc<0><<<dim3(4, 32, 2), 256, GEMM_SMEM>>>(
            pmrg, 512, 2097152, 0, pwmp + (long)i * 262144, 512, 0, 0,
            bm + i * 512, pcat + 512, 1024, 4194304, 0, nullptr, 0, 512, 1, 1.f, 0, 1);
        // MLP1 (output fp32 for instance-norm stats)
        gemm_tc<0><<<dim3(8, 32, 2), 256, GEMM_SMEM>>>(
            pcat, 1024, 4194304, 0, pW1q + (long)i * 1048576, 1024, 0, 0,
            b1 + i * 1024, pz, 1024, 4194304, 0, nullptr, 0, 1024, 1, 1.f, 0, 0);
        instnorm_relu<<<256, 256>>>();
        // MLP2 + fused residual: nxt = cur + z @ W2^T + b2  (fp32 out)
        gemm_tc<0><<<dim3(4, 32, 2), 256, GEMM_SMEM>>>(
            pz, 1024, 4194304, 0, pW2q + (long)i * 524288, 1024, 0, 0,
            b2 + i * 512, nxt, 512, 2097152, 0, cur, 2097152, 1024, 1, 1.f, 0, 0);
        float* tmp = cur; cur = nxt; nxt = tmp;
    }

    // final projection (QA=1: cur is fp32) -> quantized mfin; then score GEMM
    gemm_tc<1><<<dim3(4, 32, 2), 256, GEMM_SMEM>>>(
        cur, 512, 2097152, 0, pWfq, 512, 0, 0, bf,
        pmfin, 512, 2097152, 0, nullptr, 0, 512, 1, 1.f, 0, 1);
    gemm_tc<0><<<dim3(8, 8, 4), 256, GEMM_SMEM>>>(
        pmfin, 512, 524288, 0, pmfin + 2097152, 512, 524288, 0, nullptr,
        pcoup, 1025, 1050625, 0, nullptr, 0, 512, 1, 0.04419417382415922f, 0, 0);

    sink_init<<<33, 256>>>(bin);
    for (int it = 0; it < 100; it++) {
        sink_u<<<4100, 256>>>();
        sink_v<<<dim3(33, 4), 256>>>();
    }
    final_out<<<16417, 256>>>((float*)d_out);
}

// round 4
// speedup vs baseline: 4.5199x; 1.2652x over previous
#include <cuda_runtime.h>

// ======================= static scratch =======================
__device__ float g_act[8388608];     // 2 ping-pong [tset][4096,512] fp32 residual stream
__device__ float g_q [4194304];      // [2 tsets][4096, 512] tf32-quantized
__device__ float g_k [4194304];
__device__ float g_v [4194304];
__device__ float g_mrg[4194304];     // [2 tsets][4096, 512] head-major merged (tf32q)
__device__ float g_cat[8388608];     // [2 tsets][4096, 1024] (tf32q)
__device__ float g_z  [8388608];     // [2 tsets][4096, 1024]
__device__ float g_mfin[4194304];    // [2 sets][4096, 512] (tf32q)
__device__ float g_coup[4202500];    // [4,1025,1025]
__device__ float g_P   [4202500];    // exp(coup - rowmax)
__device__ float g_M [4100];         // row maxima
__device__ float g_w [4100];         // e^{u+M}
__device__ float g_ev[4100];         // e^{v}
__device__ float g_u [4100];
__device__ float g_vv[4100];
__device__ float g_wpack[9437184];   // [12][1536][512]  Wq|Wk|Wv (tf32q)
__device__ float g_bpack[18432];     // [12][1536]
__device__ float g_wmp[3145728];     // [12][512][512]   Wm cols permuted (tf32q)
__device__ float g_W1q[12582912];    // [12][1024][1024] (tf32q)
__device__ float g_W2q[6291456];     // [12][512][1024]  (tf32q)
__device__ float g_Wfq[262144];      // [512][512]       (tf32q)

#define NORM_C  (-7.6246189861593985f)   // -log(2048)
#define BIN_MU  (-0.6931471805599453f)   // log(1024)-log(2048)
#define LDS 36
#define GEMM_SMEM (4*128*LDS*4)
#define QPAD 68
#define KPAD 68
#define VPAD 72
#define FLASH_SMEM ((128*QPAD + 64*KPAD + 64*VPAD)*4)

// ======================= tensor-core primitives =======================
__device__ __forceinline__ unsigned f2tf(float x) {
    unsigned u; asm("cvt.rna.tf32.f32 %0, %1;" : "=r"(u) : "f"(x)); return u;
}
__device__ __forceinline__ float tfq(float x) { return __uint_as_float(f2tf(x)); }
__device__ __forceinline__ void mma8(float* d, const unsigned* a, const unsigned* b) {
    asm volatile(
        "mma.sync.aligned.m16n8k8.row.col.f32.tf32.tf32.f32 "
        "{%0,%1,%2,%3}, {%4,%5,%6,%7}, {%8,%9}, {%0,%1,%2,%3};\n"
        : "+f"(d[0]), "+f"(d[1]), "+f"(d[2]), "+f"(d[3])
        : "r"(a[0]), "r"(a[1]), "r"(a[2]), "r"(a[3]), "r"(b[0]), "r"(b[1]));
}
__device__ __forceinline__ void cpa16(float* s, const float* g) {
    unsigned sa = (unsigned)__cvta_generic_to_shared(s);
    asm volatile("cp.async.ca.shared.global [%0], [%1], 16;\n" :: "r"(sa), "l"(g));
}
#define LDSM4(d0,d1,d2,d3,addr) \
    asm volatile("ldmatrix.sync.aligned.m8n8.x4.shared.b16 {%0,%1,%2,%3}, [%4];\n" \
        : "=r"(d0), "=r"(d1), "=r"(d2), "=r"(d3) : "r"(addr))

// ======================= TF32 NT GEMM (ldmatrix fragments) ===========================
template <int QA>
__global__ __launch_bounds__(256, 2) void gemm_tc(
    const float* __restrict__ A, int lda, long aS1, long aS2,
    const float* __restrict__ B, int ldb, long bS1, long bS2,
    const float* __restrict__ bias,
    float* __restrict__ C, int ldc, long cS1, long cS2,
    const float* __restrict__ resid, long rS1,
    int K, int zmod, float alpha, int qkv_mode, int quantO)
{
    extern __shared__ float smem[];
    float* As = smem;
    float* Bs = smem + 2 * 128 * LDS;
    const int z = blockIdx.z, z1 = z / zmod, z2 = z - z1 * zmod;
    A += z1 * aS1 + z2 * aS2;
    B += z1 * bS1 + z2 * bS2;
    C += z1 * cS1 + z2 * cS2;
    if (resid) resid += z1 * rS1;
    const int tid = threadIdx.x;
    const int bm = blockIdx.y * 128, bn = blockIdx.x * 128;
    const int KT = K >> 5;

    auto issue = [&](int kt, int st) {
        const float* Ag = A + (long)bm * lda + kt * 32;
        float* as = As + st * 128 * LDS;
        #pragma unroll
        for (int i = 0; i < 4; i++) {
            int idx = tid + i * 256, r = idx >> 3, c = (idx & 7) * 4;
            cpa16(as + r * LDS + c, Ag + (long)r * lda + c);
        }
        const float* Bg = B + (long)bn * ldb + kt * 32;
        float* bs = Bs + st * 128 * LDS;
        #pragma unroll
        for (int i = 0; i < 4; i++) {
            int idx = tid + i * 256, r = idx >> 3, c = (idx & 7) * 4;
            cpa16(bs + r * LDS + c, Bg + (long)r * ldb + c);
        }
        asm volatile("cp.async.commit_group;\n");
    };

    float acc[4][4][4] = {};
    const int wid = tid >> 5, lane = tid & 31;
    const int wm = wid & 1, wn = wid >> 1, g = lane >> 2, q = lane & 3;
    const int t4 = lane >> 3, tr8 = lane & 7;
    const unsigned smem_u = (unsigned)__cvta_generic_to_shared(smem);
    unsigned a_off[4], b_off[2];
    #pragma unroll
    for (int mt = 0; mt < 4; mt++)
        a_off[mt] = smem_u + (((wm * 64 + mt * 16 + ((t4 & 1) << 3) + tr8) * LDS
                              + ((t4 >> 1) << 2)) << 2);
    #pragma unroll
    for (int p = 0; p < 2; p++)
        b_off[p] = smem_u + ((2 * 128 * LDS
                              + (wn * 32 + p * 16 + ((t4 >> 1) << 3) + tr8) * LDS
                              + ((t4 & 1) << 2)) << 2);

    issue(0, 0);
    for (int kt = 0; kt < KT; kt++) {
        int st = kt & 1;
        if (kt + 1 < KT) { issue(kt + 1, st ^ 1); asm volatile("cp.async.wait_group 1;\n"); }
        else             { asm volatile("cp.async.wait_group 0;\n"); }
        __syncthreads();
        const unsigned sb = st * (128 * LDS * 4);
        #pragma unroll
        for (int k8 = 0; k8 < 4; k8++) {
            unsigned af[4][4], bf[4][2];
            #pragma unroll
            for (int mt = 0; mt < 4; mt++) {
                LDSM4(af[mt][0], af[mt][1], af[mt][2], af[mt][3],
                      a_off[mt] + sb + k8 * 32);
                if (QA) {
                    #pragma unroll
                    for (int e = 0; e < 4; e++)
                        af[mt][e] = f2tf(__uint_as_float(af[mt][e]));
                }
            }
            #pragma unroll
            for (int p = 0; p < 2; p++)
                LDSM4(bf[2*p][0], bf[2*p][1], bf[2*p+1][0], bf[2*p+1][1],
                      b_off[p] + sb + k8 * 32);
            #pragma unroll
            for (int mt = 0; mt < 4; mt++)
                #pragma unroll
                for (int nt = 0; nt < 4; nt++) mma8(acc[mt][nt], af[mt], bf[nt]);
        }
        __syncthreads();
    }

    const long zoff = (long)blockIdx.z * 2097152;
    #pragma unroll
    for (int mt = 0; mt < 4; mt++)
        #pragma unroll
        for (int nt = 0; nt < 4; nt++) {
            int r0 = bm + wm * 64 + mt * 16 + g;
            int c0 = bn + wn * 32 + nt * 8 + q * 2;
            #pragma unroll
            for (int i2 = 0; i2 < 2; i2++) {
                int r = r0 + i2 * 8;
                #pragma unroll
                for (int j2 = 0; j2 < 2; j2++) {
                    int c = c0 + j2;
                    float v = alpha * acc[mt][nt][i2 * 2 + j2];
                    if (bias) v += bias[c];
                    if (qkv_mode) {
                        float vq = tfq(v);
                        if (c < 512)       g_q[zoff + (long)r * 512 + c] = vq;
                        else if (c < 1024) g_k[zoff + (long)r * 512 + (c - 512)] = vq;
                        else               g_v[zoff + (long)r * 512 + (c - 1024)] = vq;
                    } else {
                        if (resid) v += resid[(long)r * ldc + c];
                        if (quantO) v = tfq(v);
                        C[(long)r * ldc + c] = v;
                    }
                }
            }
        }
}

// ======================= fused flash attention =======================================
__global__ __launch_bounds__(256, 2) void flash_attn(int cross)
{
    extern __shared__ float smem[];
    float* Qs = smem;                  // [128][QPAD]
    float* Ks = smem + 128 * QPAD;     // [64][KPAD]
    float* Vs = Ks + 64 * KPAD;        // [64][VPAD]
    const int ts = blockIdx.z;
    const int os = cross ? (1 - ts) : ts;
    const int bh = blockIdx.y, b = bh >> 3, h = bh & 7;
    const int m0 = blockIdx.x * 128;
    const int tid = threadIdx.x, wid = tid >> 5, lane = tid & 31;
    const int g = lane >> 2, q = lane & 3;
    const int t4 = lane >> 3, tr8 = lane & 7;

    const float* Qg = g_q + (long)ts * 2097152 + (long)(b * 1024 + m0) * 512 + h * 64;
    const float* Kg = g_k + (long)os * 2097152 + (long)(b * 1024) * 512 + h * 64;
    const float* Vg = g_v + (long)os * 2097152 + (long)(b * 1024) * 512 + h * 64;

    #pragma unroll
    for (int i = 0; i < 8; i++) {
        int idx = tid + i * 256, r = idx >> 4, c = (idx & 15) * 4;
        cpa16(Qs + r * QPAD + c, Qg + (long)r * 512 + c);
    }
    asm volatile("cp.async.commit_group;\n");

    auto loadKV = [&](int t) {
        #pragma unroll
        for (int i = 0; i < 4; i++) {
            int idx = tid + i * 256, r = idx >> 4, c = (idx & 15) * 4;
            cpa16(Ks + r * KPAD + c, Kg + (long)(t * 64 + r) * 512 + c);
        }
        #pragma unroll
        for (int i = 0; i < 4; i++) {
            int idx = tid + i * 256, r = idx >> 4, c = (idx & 15) * 4;
            cpa16(Vs + r * VPAD + c, Vg + (long)(t * 64 + r) * 512 + c);
        }
        asm volatile("cp.async.commit_group;\n");
    };
    loadKV(0);

    const int wr = wid * 16;
    const unsigned smem_u = (unsigned)__cvta_generic_to_shared(smem);
    const unsigned aq_off = smem_u + (((wr + ((t4 & 1) << 3) + tr8) * QPAD
                                      + ((t4 >> 1) << 2)) << 2);
    unsigned bk_off[4];
    #pragma unroll
    for (int p = 0; p < 4; p++)
        bk_off[p] = smem_u + ((128 * QPAD
                               + (p * 16 + ((t4 >> 1) << 3) + tr8) * KPAD
                               + ((t4 & 1) << 2)) << 2);

    float mp0 = -1e30f, mp1 = -1e30f, l0 = 0.f, l1 = 0.f;
    float o[8][4] = {};

    for (int t = 0; t < 16; t++) {
        asm volatile("cp.async.wait_group 0;\n");
        __syncthreads();
        float s[8][4] = {};
        #pragma unroll
        for (int j = 0; j < 8; j++) {
            unsigned aq[4];
            LDSM4(aq[0], aq[1], aq[2], aq[3], aq_off + j * 32);
            #pragma unroll
            for (int p = 0; p < 4; p++) {
                unsigned bk0[2], bk1[2];
                LDSM4(bk0[0], bk0[1], bk1[0], bk1[1], bk_off[p] + j * 32);
                mma8(s[2*p],   aq, bk0);
                mma8(s[2*p+1], aq, bk1);
            }
        }
        // scale + online softmax
        float lm0 = -1e30f, lm1 = -1e30f;
        #pragma unroll
        for (int nt = 0; nt < 8; nt++) {
            #pragma unroll
            for (int e = 0; e < 4; e++) s[nt][e] *= 0.125f;
            lm0 = fmaxf(lm0, fmaxf(s[nt][0], s[nt][1]));
            lm1 = fmaxf(lm1, fmaxf(s[nt][2], s[nt][3]));
        }
        lm0 = fmaxf(lm0, __shfl_xor_sync(0xffffffff, lm0, 1));
        lm0 = fmaxf(lm0, __shfl_xor_sync(0xffffffff, lm0, 2));
        lm1 = fmaxf(lm1, __shfl_xor_sync(0xffffffff, lm1, 1));
        lm1 = fmaxf(lm1, __shfl_xor_sync(0xffffffff, lm1, 2));
        float mn0 = fmaxf(mp0, lm0), mn1 = fmaxf(mp1, lm1);
        float a0 = __expf(mp0 - mn0), a1 = __expf(mp1 - mn1);
        float ps0 = 0.f, ps1 = 0.f;
        #pragma unroll
        for (int nt = 0; nt < 8; nt++) {
            s[nt][0] = __expf(s[nt][0] - mn0);
            s[nt][1] = __expf(s[nt][1] - mn0);
            s[nt][2] = __expf(s[nt][2] - mn1);
            s[nt][3] = __expf(s[nt][3] - mn1);
            ps0 += s[nt][0] + s[nt][1];
            ps1 += s[nt][2] + s[nt][3];
        }
        ps0 += __shfl_xor_sync(0xffffffff, ps0, 1);
        ps0 += __shfl_xor_sync(0xffffffff, ps0, 2);
        ps1 += __shfl_xor_sync(0xffffffff, ps1, 1);
        ps1 += __shfl_xor_sync(0xffffffff, ps1, 2);
        l0 = l0 * a0 + ps0;  l1 = l1 * a1 + ps1;
        mp0 = mn0;  mp1 = mn1;
        #pragma unroll
        for (int tt = 0; tt < 8; tt++) {
            o[tt][0] *= a0; o[tt][1] *= a0; o[tt][2] *= a1; o[tt][3] *= a1;
        }
        // PV: A-frag from s[j] via quad shuffles
        const int srcA = (lane & ~3) | (q >> 1);
        const int srcB = srcA + 2;
        const bool odd = q & 1;
        #pragma unroll
        for (int j = 0; j < 8; j++) {
            float v00 = __shfl_sync(0xffffffff, s[j][0], srcA);
            float v01 = __shfl_sync(0xffffffff, s[j][1], srcA);
            float v10 = __shfl_sync(0xffffffff, s[j][2], srcA);
            float v11 = __shfl_sync(0xffffffff, s[j][3], srcA);
            float w00 = __shfl_sync(0xffffffff, s[j][0], srcB);
            float w01 = __shfl_sync(0xffffffff, s[j][1], srcB);
            float w10 = __shfl_sync(0xffffffff, s[j][2], srcB);
            float w11 = __shfl_sync(0xffffffff, s[j][3], srcB);
            unsigned ap[4];
            ap[0] = f2tf(odd ? v01 : v00);
            ap[1] = f2tf(odd ? v11 : v10);
            ap[2] = f2tf(odd ? w01 : w00);
            ap[3] = f2tf(odd ? w11 : w10);
            #pragma unroll
            for (int tt = 0; tt < 8; tt++) {
                unsigned bv[2];
                bv[0] = __float_as_uint(Vs[(j * 8 + q) * VPAD + tt * 8 + g]);
                bv[1] = __float_as_uint(Vs[(j * 8 + q + 4) * VPAD + tt * 8 + g]);
                mma8(o[tt], ap, bv);
            }
        }
        __syncthreads();
        if (t < 15) loadKV(t + 1);
    }

    float inv0 = 1.f / l0, inv1 = 1.f / l1;
    float* Og = g_mrg + (long)ts * 2097152 + (long)(b * 1024 + m0 + wr) * 512 + h * 64;
    #pragma unroll
    for (int tt = 0; tt < 8; tt++) {
        int c = tt * 8 + q * 2;
        Og[(long)g * 512 + c]           = tfq(o[tt][0] * inv0);
        Og[(long)g * 512 + c + 1]       = tfq(o[tt][1] * inv0);
        Og[(long)(g + 8) * 512 + c]     = tfq(o[tt][2] * inv1);
        Og[(long)(g + 8) * 512 + c + 1] = tfq(o[tt][3] * inv1);
    }
}

// ======================= weight pack / quantize ======================================
__global__ void pack_w(const float* __restrict__ Wq, const float* __restrict__ Wk,
                       const float* __restrict__ Wv, const float* __restrict__ bq,
                       const float* __restrict__ bk, const float* __restrict__ bv,
                       const float* __restrict__ Wm, const float* __restrict__ W1,
                       const float* __restrict__ W2, const float* __restrict__ Wf)
{
    long t = (long)blockIdx.x * 256 + threadIdx.x;
    if (t < 9437184) {
        long i = t / 786432; long rem = t - i * 786432;
        int row = (int)(rem >> 9), d = (int)(rem & 511);
        const float* src = row < 512 ? Wq : (row < 1024 ? Wk : Wv);
        g_wpack[t] = tfq(src[i * 262144 + (long)(row & 511) * 512 + d]);
    }
    if (t < 18432) {
        long i = t / 1536; int row = (int)(t - i * 1536);
        const float* sb = row < 512 ? bq : (row < 1024 ? bk : bv);
        g_bpack[t] = sb[i * 512 + (row & 511)];
    }
    if (t < 3145728) {
        long i = t >> 18; long rem = t & 262143;
        int o = (int)(rem >> 9), c = (int)(rem & 511);
        g_wmp[t] = tfq(Wm[i * 262144 + (long)o * 512 + (c & 63) * 8 + (c >> 6)]);
    }
    if (t < 12582912) g_W1q[t] = tfq(W1[t]);
    if (t < 6291456)  g_W2q[t] = tfq(W2[t]);
    if (t < 262144)   g_Wfq[t] = tfq(Wf[t]);
}

// ======================= InstanceNorm1d + ReLU (writes tf32q) ========================
__global__ __launch_bounds__(256) void instnorm_relu()
{
    int bb = blockIdx.x >> 5;
    int gch = blockIdx.x & 31;
    int lane = threadIdx.x & 31, w = threadIdx.x >> 5;
    int c = gch * 32 + lane;
    float* base = g_z + (long)bb * 1048576 + c;
    float s = 0.f;
    for (int n = w; n < 1024; n += 8) s += base[(long)n * 1024];
    __shared__ float sh[8][32];
    sh[w][lane] = s; __syncthreads();
    if (w == 0) { float a = 0; for (int i = 0; i < 8; i++) a += sh[i][lane]; sh[0][lane] = a * (1.f/1024.f); }
    __syncthreads();
    float mean = sh[0][lane];
    __syncthreads();
    float s2 = 0.f;
    for (int n = w; n < 1024; n += 8) { float d = base[(long)n * 1024] - mean; s2 += d * d; }
    sh[w][lane] = s2; __syncthreads();
    if (w == 0) { float a = 0; for (int i = 0; i < 8; i++) a += sh[i][lane];
                  sh[0][lane] = rsqrtf(a * (1.f/1024.f) + 1e-5f); }
    __syncthreads();
    float inv = sh[0][lane];
    for (int n = w; n < 1024; n += 8) {
        long off = (long)n * 1024;
        base[off] = tfq(fmaxf((base[off] - mean) * inv, 0.f));
    }
}

// ======================= elementwise helpers =========================================
__global__ void copy4(float4* __restrict__ dst, const float4* __restrict__ src)
{
    long t = (long)blockIdx.x * 256 + threadIdx.x;
    dst[t] = src[t];
}
__global__ void copy_to_cat(const float4* __restrict__ x)
{
    long t = (long)blockIdx.x * 256 + threadIdx.x;
    long ts = t >> 19, rem = t & 524287;
    long r = rem >> 7, c = rem & 127;
    float4 v = x[ts * 524288 + rem];
    v.x = tfq(v.x); v.y = tfq(v.y); v.z = tfq(v.z); v.w = tfq(v.w);
    ((float4*)g_cat)[ts * 1048576 + r * 256 + c] = v;
}

// ======================= Sinkhorn (exp-domain, transcendental-free loop) =============
__global__ void sink_init(const float* __restrict__ bin)
{
    float a = *bin;
    int t = blockIdx.x * 256 + threadIdx.x;
    if (t < 4100) g_ev[t] = 1.f;                       // e^{v}, v=0
    if (t < 8196) {
        int b = t / 2049, r = t - b * 2049;
        float* cb = g_coup + (long)b * 1050625;
        if (r < 1024) cb[(long)r * 1025 + 1024] = a;
        else          cb[(long)1024 * 1025 + (r - 1024)] = a;
    }
}

// per row: M = max, P = exp(C - M)
__global__ __launch_bounds__(256) void sink_prep()
{
    int r = blockIdx.x;
    int b = r / 1025, i = r - b * 1025;
    const float* row = g_coup + (long)b * 1050625 + (long)i * 1025;
    float* prow = g_P + (long)b * 1050625 + (long)i * 1025;
    int t = threadIdx.x;
    float m = -1e30f;
    for (int j = t; j < 1025; j += 256) m = fmaxf(m, row[j]);
    __shared__ float sm[256];
    sm[t] = m; __syncthreads();
    for (int o = 128; o > 0; o >>= 1) { if (t < o) sm[t] = fmaxf(sm[t], sm[t+o]); __syncthreads(); }
    m = sm[0];
    if (t == 0) g_M[r] = m;
    for (int j = t; j < 1025; j += 256) prow[j] = __expf(row[j] - m);
}

// u-step: w_i = mu_i / (P_i,: . ev)
__global__ __launch_bounds__(256) void sink_row()
{
    const int b = blockIdx.y, g0 = blockIdx.x * 32;
    __shared__ float ev[1025];
    const int t = threadIdx.x;
    for (int j = t; j < 1025; j += 256) ev[j] = g_ev[b * 1025 + j];
    __syncthreads();
    const int w = t >> 5, lane = t & 31;
    for (int rr = w; rr < 32; rr += 8) {
        int i = g0 + rr;
        if (i >= 1025) break;
        const float* prow = g_P + (long)b * 1050625 + (long)i * 1025;
        float s = 0.f;
        for (int j = lane; j < 1025; j += 32) s += prow[j] * ev[j];
        #pragma unroll
        for (int o = 16; o > 0; o >>= 1) s += __shfl_xor_sync(0xffffffff, s, o);
        if (lane == 0)
            g_w[b * 1025 + i] = (i < 1024 ? (1.f / 2048.f) : 0.5f) / s;
    }
}

// v-step: ev_j = nu_j / (P_:,j . w)
__global__ __launch_bounds__(256) void sink_col()
{
    const int b = blockIdx.y, j0 = blockIdx.x * 32;
    __shared__ float ws[1025];
    const int t = threadIdx.x;
    for (int i = t; i < 1025; i += 256) ws[i] = g_w[b * 1025 + i];
    __syncthreads();
    const int lane = t & 31, sl = t >> 5;
    const int j = j0 + lane;
    float s = 0.f;
    if (j < 1025) {
        const float* pb = g_P + (long)b * 1050625 + j;
        for (int i = sl; i < 1025; i += 8) s += pb[(long)i * 1025] * ws[i];
    }
    __shared__ float red[8][32];
    red[sl][lane] = s; __syncthreads();
    if (sl == 0 && j < 1025) {
        float S = s;
        #pragma unroll
        for (int k = 1; k < 8; k++) S += red[k][lane];
        g_ev[b * 1025 + j] = (j < 1024 ? (1.f / 2048.f) : 0.5f) / S;
    }
}

__global__ void sink_uvfin()
{
    int t = blockIdx.x * 256 + threadIdx.x;
    if (t < 4100) {
        g_u[t]  = logf(g_w[t]) - g_M[t];
        g_vv[t] = logf(g_ev[t]);
    }
}

__global__ void final_out(float* __restrict__ out)
{
    long t = (long)blockIdx.x * 256 + threadIdx.x;
    if (t >= 4202500L) return;
    int b = (int)(t / 1050625);
    int rem = (int)(t - (long)b * 1050625);
    int i = rem / 1025, j = rem - i * 1025;
    out[t] = g_coup[t] + g_u[b * 1025 + i] + g_vv[b * 1025 + j] - NORM_C;
}

// ======================= driver ======================================================
extern "C" void kernel_launch(void* const* d_in, const int* in_sizes, int n_in,
                              void* d_out, int out_size)
{
    (void)in_sizes; (void)n_in; (void)out_size;
    const float* Wq = (const float*)d_in[2];  const float* bq = (const float*)d_in[3];
    const float* Wk = (const float*)d_in[4];  const float* bk = (const float*)d_in[5];
    const float* Wv = (const float*)d_in[6];  const float* bv = (const float*)d_in[7];
    const float* Wm = (const float*)d_in[8];  const float* bm = (const float*)d_in[9];
    const float* W1 = (const float*)d_in[10]; const float* b1 = (const float*)d_in[11];
    const float* W2 = (const float*)d_in[12]; const float* b2 = (const float*)d_in[13];
    const float* Wf = (const float*)d_in[14]; const float* bf = (const float*)d_in[15];
    const float* bin = (const float*)d_in[16];

    cudaFuncSetAttribute(gemm_tc<0>, cudaFuncAttributeMaxDynamicSharedMemorySize, GEMM_SMEM);
    cudaFuncSetAttribute(gemm_tc<1>, cudaFuncAttributeMaxDynamicSharedMemorySize, GEMM_SMEM);
    cudaFuncSetAttribute(flash_attn, cudaFuncAttributeMaxDynamicSharedMemorySize, FLASH_SMEM);

    float *pact, *pcat, *pz, *pmfin, *pcoup, *pwpack, *pbpack, *pwmp, *pW1q, *pW2q, *pWfq, *pmrg;
    cudaGetSymbolAddress((void**)&pact,  g_act);
    cudaGetSymbolAddress((void**)&pcat,  g_cat);
    cudaGetSymbolAddress((void**)&pz,    g_z);
    cudaGetSymbolAddress((void**)&pmfin, g_mfin);
    cudaGetSymbolAddress((void**)&pcoup, g_coup);
    cudaGetSymbolAddress((void**)&pwpack,g_wpack);
    cudaGetSymbolAddress((void**)&pbpack,g_bpack);
    cudaGetSymbolAddress((void**)&pwmp,  g_wmp);
    cudaGetSymbolAddress((void**)&pW1q,  g_W1q);
    cudaGetSymbolAddress((void**)&pW2q,  g_W2q);
    cudaGetSymbolAddress((void**)&pWfq,  g_Wfq);
    cudaGetSymbolAddress((void**)&pmrg,  g_mrg);

    pack_w<<<49152, 256>>>(Wq, Wk, Wv, bq, bk, bv, Wm, W1, W2, Wf);

    float* cur = pact;
    float* nxt = pact + 4194304;
    copy4<<<2048, 256>>>((float4*)cur,             (const float4*)d_in[0]);
    copy4<<<2048, 256>>>((float4*)(cur + 2097152), (const float4*)d_in[1]);

    for (int i = 0; i < 12; i++) {
        const int cross = (i & 1);
        gemm_tc<1><<<dim3(12, 32, 2), 256, GEMM_SMEM>>>(
            cur, 512, 2097152, 0, pwpack + (long)i * 786432, 512, 0, 0,
            pbpack + i * 1536, nullptr, 0, 0, 0, nullptr, 0, 512, 1, 1.f, 1, 0);
        flash_attn<<<dim3(8, 32, 2), 256, FLASH_SMEM>>>(cross);
        copy_to_cat<<<4096, 256>>>((const float4*)cur);
        gemm_tc<0><<<dim3(4, 32, 2), 256, GEMM_SMEM>>>(
            pmrg, 512, 2097152, 0, pwmp + (long)i * 262144, 512, 0, 0,
            bm + i * 512, pcat + 512, 1024, 4194304, 0, nullptr, 0, 512, 1, 1.f, 0, 1);
        gemm_tc<0><<<dim3(8, 32, 2), 256, GEMM_SMEM>>>(
            pcat, 1024, 4194304, 0, pW1q + (long)i * 1048576, 1024, 0, 0,
            b1 + i * 1024, pz, 1024, 4194304, 0, nullptr, 0, 1024, 1, 1.f, 0, 0);
        instnorm_relu<<<256, 256>>>();
        gemm_tc<0><<<dim3(4, 32, 2), 256, GEMM_SMEM>>>(
            pz, 1024, 4194304, 0, pW2q + (long)i * 524288, 1024, 0, 0,
            b2 + i * 512, nxt, 512, 2097152, 0, cur, 2097152, 1024, 1, 1.f, 0, 0);
        float* tmp = cur; cur = nxt; nxt = tmp;
    }

    gemm_tc<1><<<dim3(4, 32, 2), 256, GEMM_SMEM>>>(
        cur, 512, 2097152, 0, pWfq, 512, 0, 0, bf,
        pmfin, 512, 2097152, 0, nullptr, 0, 512, 1, 1.f, 0, 1);
    gemm_tc<0><<<dim3(8, 8, 4), 256, GEMM_SMEM>>>(
        pmfin, 512, 524288, 0, pmfin + 2097152, 512, 524288, 0, nullptr,
        pcoup, 1025, 1050625, 0, nullptr, 0, 512, 1, 0.04419417382415922f, 0, 0);

    sink_init<<<33, 256>>>(bin);
    sink_prep<<<4100, 256>>>();
    for (int it = 0; it < 100; it++) {
        sink_row<<<dim3(33, 4), 256>>>();
        sink_col<<<dim3(33, 4), 256>>>();
    }
    sink_uvfin<<<17, 256>>>();
    final_out<<<16417, 256>>>((float*)d_out);
}

// round 5
// speedup vs baseline: 4.8353x; 1.0698x over previous
#include <cuda_runtime.h>
#include <cuda_bf16.h>

// ======================= static scratch =======================
__device__ float g_act[8388608];     // 2 ping-pong [tset][4096,512] fp32 residual stream
__device__ float g_q [4194304];      // [2 tsets][4096, 512] tf32-quantized
__device__ float g_k [4194304];
__device__ float g_v [4194304];
__device__ float g_cat[8388608];     // [2 tsets][4096, 1024]: [:,:512]=x_q, [:,512:]=mrg_q
__device__ float g_z  [8388608];     // [2 tsets][4096, 1024]
__device__ float g_mfin[4194304];    // [2 sets][4096, 512] (tf32q)
__device__ float g_coup[4202500];    // [4,1025,1025]
__device__ __nv_bfloat16 g_Pb [4202500];   // exp(coup - rowmax), bf16
__device__ __nv_bfloat16 g_PTb[4202500];   // transpose of g_Pb
__device__ float g_M [4100];
__device__ float g_w [4100];
__device__ float g_ev[4100];
__device__ float g_u [4100];
__device__ float g_vv[4100];
__device__ unsigned g_ctr;
__device__ float g_wpack[9437184];   // [12][1536][512]  Wq|Wk|Wv (tf32q)
__device__ float g_bpack[18432];     // [12][1536]
__device__ float g_wmt[3145728];     // [12][512(c)][512(o)] = Wm[o][perm(c)] (tf32q)
__device__ float g_W1c[12582912];    // [12][1024][1024]: [:, :512]=W1a_q, [:,512:]=W1b@Wm_q
__device__ float g_b1f[12288];       // [12][1024] = b1 + W1b@bm
__device__ float g_W2q[6291456];     // [12][512][1024]  (tf32q)
__device__ float g_Wfq[262144];      // [512][512]       (tf32q)

#define NORM_C  (-7.6246189861593985f)   // -log(2048)
#define LDS 36
#define GEMM_SMEM (4*128*LDS*4)
#define QPAD 68
#define KPAD 68
#define VPAD 72
#define FLASH_SMEM ((128*QPAD + 64*KPAD + 64*VPAD)*4)

// ======================= tensor-core primitives =======================
__device__ __forceinline__ unsigned f2tf(float x) {
    unsigned u; asm("cvt.rna.tf32.f32 %0, %1;" : "=r"(u) : "f"(x)); return u;
}
__device__ __forceinline__ float tfq(float x) { return __uint_as_float(f2tf(x)); }
__device__ __forceinline__ void mma8(float* d, const unsigned* a, const unsigned* b) {
    asm volatile(
        "mma.sync.aligned.m16n8k8.row.col.f32.tf32.tf32.f32 "
        "{%0,%1,%2,%3}, {%4,%5,%6,%7}, {%8,%9}, {%0,%1,%2,%3};\n"
        : "+f"(d[0]), "+f"(d[1]), "+f"(d[2]), "+f"(d[3])
        : "r"(a[0]), "r"(a[1]), "r"(a[2]), "r"(a[3]), "r"(b[0]), "r"(b[1]));
}
__device__ __forceinline__ void cpa16(float* s, const float* g) {
    unsigned sa = (unsigned)__cvta_generic_to_shared(s);
    asm volatile("cp.async.ca.shared.global [%0], [%1], 16;\n" :: "r"(sa), "l"(g));
}
#define LDSM4(d0,d1,d2,d3,addr) \
    asm volatile("ldmatrix.sync.aligned.m8n8.x4.shared.b16 {%0,%1,%2,%3}, [%4];\n" \
        : "=r"(d0), "=r"(d1), "=r"(d2), "=r"(d3) : "r"(addr))

// ======================= TF32 NT GEMM (ldmatrix fragments) ===========================
template <int QA>
__global__ __launch_bounds__(256, 2) void gemm_tc(
    const float* __restrict__ A, int lda, long aS1, long aS2,
    const float* __restrict__ B, int ldb, long bS1, long bS2,
    const float* __restrict__ bias,
    float* __restrict__ C, int ldc, long cS1, long cS2,
    const float* __restrict__ resid, long rS1,
    int K, int zmod, float alpha, int qkv_mode, int quantO,
    float* __restrict__ Cq, long cqS1)
{
    extern __shared__ float smem[];
    float* As = smem;
    const int z = blockIdx.z, z1 = z / zmod, z2 = z - z1 * zmod;
    A += z1 * aS1 + z2 * aS2;
    B += z1 * bS1 + z2 * bS2;
    C += z1 * cS1 + z2 * cS2;
    if (resid) resid += z1 * rS1;
    if (Cq)    Cq    += z1 * cqS1;
    const int tid = threadIdx.x;
    const int bm = blockIdx.y * 128, bn = blockIdx.x * 128;
    const int KT = K >> 5;

    auto issue = [&](int kt, int st) {
        const float* Ag = A + (long)bm * lda + kt * 32;
        float* as = As + st * 128 * LDS;
        #pragma unroll
        for (int i = 0; i < 4; i++) {
            int idx = tid + i * 256, r = idx >> 3, c = (idx & 7) * 4;
            cpa16(as + r * LDS + c, Ag + (long)r * lda + c);
        }
        const float* Bg = B + (long)bn * ldb + kt * 32;
        float* bs = As + 2 * 128 * LDS + st * 128 * LDS;
        #pragma unroll
        for (int i = 0; i < 4; i++) {
            int idx = tid + i * 256, r = idx >> 3, c = (idx & 7) * 4;
            cpa16(bs + r * LDS + c, Bg + (long)r * ldb + c);
        }
        asm volatile("cp.async.commit_group;\n");
    };

    float acc[4][4][4] = {};
    const int wid = tid >> 5, lane = tid & 31;
    const int wm = wid & 1, wn = wid >> 1, g = lane >> 2, q = lane & 3;
    const int t4 = lane >> 3, tr8 = lane & 7;
    const unsigned smem_u = (unsigned)__cvta_generic_to_shared(smem);
    unsigned a_off[4], b_off[2];
    #pragma unroll
    for (int mt = 0; mt < 4; mt++)
        a_off[mt] = smem_u + (((wm * 64 + mt * 16 + ((t4 & 1) << 3) + tr8) * LDS
                              + ((t4 >> 1) << 2)) << 2);
    #pragma unroll
    for (int p = 0; p < 2; p++)
        b_off[p] = smem_u + ((2 * 128 * LDS
                              + (wn * 32 + p * 16 + ((t4 >> 1) << 3) + tr8) * LDS
                              + ((t4 & 1) << 2)) << 2);

    issue(0, 0);
    for (int kt = 0; kt < KT; kt++) {
        int st = kt & 1;
        if (kt + 1 < KT) { issue(kt + 1, st ^ 1); asm volatile("cp.async.wait_group 1;\n"); }
        else             { asm volatile("cp.async.wait_group 0;\n"); }
        __syncthreads();
        const unsigned sb = st * (128 * LDS * 4);
        #pragma unroll
        for (int k8 = 0; k8 < 4; k8++) {
            unsigned af[4][4], bf[4][2];
            #pragma unroll
            for (int mt = 0; mt < 4; mt++) {
                LDSM4(af[mt][0], af[mt][1], af[mt][2], af[mt][3],
                      a_off[mt] + sb + k8 * 32);
                if (QA) {
                    #pragma unroll
                    for (int e = 0; e < 4; e++)
                        af[mt][e] = f2tf(__uint_as_float(af[mt][e]));
                }
            }
            #pragma unroll
            for (int p = 0; p < 2; p++)
                LDSM4(bf[2*p][0], bf[2*p][1], bf[2*p+1][0], bf[2*p+1][1],
                      b_off[p] + sb + k8 * 32);
            #pragma unroll
            for (int mt = 0; mt < 4; mt++)
                #pragma unroll
                for (int nt = 0; nt < 4; nt++) mma8(acc[mt][nt], af[mt], bf[nt]);
        }
        __syncthreads();
    }

    const long zoff = (long)blockIdx.z * 2097152;
    #pragma unroll
    for (int mt = 0; mt < 4; mt++)
        #pragma unroll
        for (int nt = 0; nt < 4; nt++) {
            int r0 = bm + wm * 64 + mt * 16 + g;
            int c0 = bn + wn * 32 + nt * 8 + q * 2;
            #pragma unroll
            for (int i2 = 0; i2 < 2; i2++) {
                int r = r0 + i2 * 8;
                #pragma unroll
                for (int j2 = 0; j2 < 2; j2++) {
                    int c = c0 + j2;
                    float v = alpha * acc[mt][nt][i2 * 2 + j2];
                    if (bias) v += bias[c];
                    if (qkv_mode) {
                        float vq = tfq(v);
                        if (c < 512)       g_q[zoff + (long)r * 512 + c] = vq;
                        else if (c < 1024) g_k[zoff + (long)r * 512 + (c - 512)] = vq;
                        else               g_v[zoff + (long)r * 512 + (c - 1024)] = vq;
                    } else {
                        if (resid) v += resid[(long)r * ldc + c];
                        if (quantO) v = tfq(v);
                        C[(long)r * ldc + c] = v;
                        if (Cq) Cq[(long)r * 1024 + c] = tfq(v);
                    }
                }
            }
        }
}

// ======================= fused flash attention (writes into g_cat msg half) ==========
__global__ __launch_bounds__(256, 2) void flash_attn(int cross)
{
    extern __shared__ float smem[];
    float* Qs = smem;                  // [128][QPAD]
    float* Ks = smem + 128 * QPAD;     // [64][KPAD]
    float* Vs = Ks + 64 * KPAD;        // [64][VPAD]
    const int ts = blockIdx.z;
    const int os = cross ? (1 - ts) : ts;
    const int bh = blockIdx.y, b = bh >> 3, h = bh & 7;
    const int m0 = blockIdx.x * 128;
    const int tid = threadIdx.x, wid = tid >> 5, lane = tid & 31;
    const int g = lane >> 2, q = lane & 3;
    const int t4 = lane >> 3, tr8 = lane & 7;

    const float* Qg = g_q + (long)ts * 2097152 + (long)(b * 1024 + m0) * 512 + h * 64;
    const float* Kg = g_k + (long)os * 2097152 + (long)(b * 1024) * 512 + h * 64;
    const float* Vg = g_v + (long)os * 2097152 + (long)(b * 1024) * 512 + h * 64;

    #pragma unroll
    for (int i = 0; i < 8; i++) {
        int idx = tid + i * 256, r = idx >> 4, c = (idx & 15) * 4;
        cpa16(Qs + r * QPAD + c, Qg + (long)r * 512 + c);
    }
    asm volatile("cp.async.commit_group;\n");

    auto loadKV = [&](int t) {
        #pragma unroll
        for (int i = 0; i < 4; i++) {
            int idx = tid + i * 256, r = idx >> 4, c = (idx & 15) * 4;
            cpa16(Ks + r * KPAD + c, Kg + (long)(t * 64 + r) * 512 + c);
        }
        #pragma unroll
        for (int i = 0; i < 4; i++) {
            int idx = tid + i * 256, r = idx >> 4, c = (idx & 15) * 4;
            cpa16(Vs + r * VPAD + c, Vg + (long)(t * 64 + r) * 512 + c);
        }
        asm volatile("cp.async.commit_group;\n");
    };
    loadKV(0);

    const int wr = wid * 16;
    const unsigned smem_u = (unsigned)__cvta_generic_to_shared(smem);
    const unsigned aq_off = smem_u + (((wr + ((t4 & 1) << 3) + tr8) * QPAD
                                      + ((t4 >> 1) << 2)) << 2);
    unsigned bk_off[4];
    #pragma unroll
    for (int p = 0; p < 4; p++)
        bk_off[p] = smem_u + ((128 * QPAD
                               + (p * 16 + ((t4 >> 1) << 3) + tr8) * KPAD
                               + ((t4 & 1) << 2)) << 2);

    float mp0 = -1e30f, mp1 = -1e30f, l0 = 0.f, l1 = 0.f;
    float o[8][4] = {};

    for (int t = 0; t < 16; t++) {
        asm volatile("cp.async.wait_group 0;\n");
        __syncthreads();
        float s[8][4] = {};
        #pragma unroll
        for (int j = 0; j < 8; j++) {
            unsigned aq[4];
            LDSM4(aq[0], aq[1], aq[2], aq[3], aq_off + j * 32);
            #pragma unroll
            for (int p = 0; p < 4; p++) {
                unsigned bk0[2], bk1[2];
                LDSM4(bk0[0], bk0[1], bk1[0], bk1[1], bk_off[p] + j * 32);
                mma8(s[2*p],   aq, bk0);
                mma8(s[2*p+1], aq, bk1);
            }
        }
        float lm0 = -1e30f, lm1 = -1e30f;
        #pragma unroll
        for (int nt = 0; nt < 8; nt++) {
            #pragma unroll
            for (int e = 0; e < 4; e++) s[nt][e] *= 0.125f;
            lm0 = fmaxf(lm0, fmaxf(s[nt][0], s[nt][1]));
            lm1 = fmaxf(lm1, fmaxf(s[nt][2], s[nt][3]));
        }
        lm0 = fmaxf(lm0, __shfl_xor_sync(0xffffffff, lm0, 1));
        lm0 = fmaxf(lm0, __shfl_xor_sync(0xffffffff, lm0, 2));
        lm1 = fmaxf(lm1, __shfl_xor_sync(0xffffffff, lm1, 1));
        lm1 = fmaxf(lm1, __shfl_xor_sync(0xffffffff, lm1, 2));
        float mn0 = fmaxf(mp0, lm0), mn1 = fmaxf(mp1, lm1);
        float a0 = __expf(mp0 - mn0), a1 = __expf(mp1 - mn1);
        float ps0 = 0.f, ps1 = 0.f;
        #pragma unroll
        for (int nt = 0; nt < 8; nt++) {
            s[nt][0] = __expf(s[nt][0] - mn0);
            s[nt][1] = __expf(s[nt][1] - mn0);
            s[nt][2] = __expf(s[nt][2] - mn1);
            s[nt][3] = __expf(s[nt][3] - mn1);
            ps0 += s[nt][0] + s[nt][1];
            ps1 += s[nt][2] + s[nt][3];
        }
        ps0 += __shfl_xor_sync(0xffffffff, ps0, 1);
        ps0 += __shfl_xor_sync(0xffffffff, ps0, 2);
        ps1 += __shfl_xor_sync(0xffffffff, ps1, 1);
        ps1 += __shfl_xor_sync(0xffffffff, ps1, 2);
        l0 = l0 * a0 + ps0;  l1 = l1 * a1 + ps1;
        mp0 = mn0;  mp1 = mn1;
        #pragma unroll
        for (int tt = 0; tt < 8; tt++) {
            o[tt][0] *= a0; o[tt][1] *= a0; o[tt][2] *= a1; o[tt][3] *= a1;
        }
        const int srcA = (lane & ~3) | (q >> 1);
        const int srcB = srcA + 2;
        const bool odd = q & 1;
        #pragma unroll
        for (int j = 0; j < 8; j++) {
            float v00 = __shfl_sync(0xffffffff, s[j][0], srcA);
            float v01 = __shfl_sync(0xffffffff, s[j][1], srcA);
            float v10 = __shfl_sync(0xffffffff, s[j][2], srcA);
            float v11 = __shfl_sync(0xffffffff, s[j][3], srcA);
            float w00 = __shfl_sync(0xffffffff, s[j][0], srcB);
            float w01 = __shfl_sync(0xffffffff, s[j][1], srcB);
            float w10 = __shfl_sync(0xffffffff, s[j][2], srcB);
            float w11 = __shfl_sync(0xffffffff, s[j][3], srcB);
            unsigned ap[4];
            ap[0] = f2tf(odd ? v01 : v00);
            ap[1] = f2tf(odd ? v11 : v10);
            ap[2] = f2tf(odd ? w01 : w00);
            ap[3] = f2tf(odd ? w11 : w10);
            #pragma unroll
            for (int tt = 0; tt < 8; tt++) {
                unsigned bv[2];
                bv[0] = __float_as_uint(Vs[(j * 8 + q) * VPAD + tt * 8 + g]);
                bv[1] = __float_as_uint(Vs[(j * 8 + q + 4) * VPAD + tt * 8 + g]);
                mma8(o[tt], ap, bv);
            }
        }
        __syncthreads();
        if (t < 15) loadKV(t + 1);
    }

    float inv0 = 1.f / l0, inv1 = 1.f / l1;
    float* Og = g_cat + (long)ts * 4194304
              + (long)(b * 1024 + m0 + wr) * 1024 + 512 + h * 64;
    #pragma unroll
    for (int tt = 0; tt < 8; tt++) {
        int c = tt * 8 + q * 2;
        Og[(long)g * 1024 + c]           = tfq(o[tt][0] * inv0);
        Og[(long)g * 1024 + c + 1]       = tfq(o[tt][1] * inv0);
        Og[(long)(g + 8) * 1024 + c]     = tfq(o[tt][2] * inv1);
        Og[(long)(g + 8) * 1024 + c + 1] = tfq(o[tt][3] * inv1);
    }
}

// ======================= weight pack / quantize ======================================
__global__ void pack_w(const float* __restrict__ Wq, const float* __restrict__ Wk,
                       const float* __restrict__ Wv, const float* __restrict__ bq,
                       const float* __restrict__ bk, const float* __restrict__ bv,
                       const float* __restrict__ Wm, const float* __restrict__ W1,
                       const float* __restrict__ W2, const float* __restrict__ Wf)
{
    long t = (long)blockIdx.x * 256 + threadIdx.x;
    if (t < 9437184) {
        long i = t / 786432; long rem = t - i * 786432;
        int row = (int)(rem >> 9), d = (int)(rem & 511);
        const float* src = row < 512 ? Wq : (row < 1024 ? Wk : Wv);
        g_wpack[t] = tfq(src[i * 262144 + (long)(row & 511) * 512 + d]);
    }
    if (t < 18432) {
        long i = t / 1536; int row = (int)(t - i * 1536);
        const float* sb = row < 512 ? bq : (row < 1024 ? bk : bv);
        g_bpack[t] = sb[i * 512 + (row & 511)];
    }
    if (t < 3145728) {           // g_wmt[i][c][o] = Wm[i][o][perm(c)]
        long i = t >> 18; long rem = t & 262143;
        int c = (int)(rem >> 9), o = (int)(rem & 511);
        int s = (c & 63) * 8 + (c >> 6);
        g_wmt[t] = tfq(Wm[i * 262144 + (long)o * 512 + s]);
    }
    if (t < 6291456) {           // W1a quantized -> g_W1c[:, :512]
        long i = t / 524288; long rem = t - i * 524288;
        int r = (int)(rem >> 9), c = (int)(rem & 511);
        g_W1c[i * 1048576 + (long)r * 1024 + c] = tfq(W1[i * 1048576 + (long)r * 1024 + c]);
    }
    if (t < 6291456)  g_W2q[t] = tfq(W2[t]);
    if (t < 262144)   g_Wfq[t] = tfq(Wf[t]);
}

// b1' = b1 + W1b @ bm (warp per output)
__global__ void fold_b1(const float* __restrict__ W1, const float* __restrict__ b1,
                        const float* __restrict__ bm)
{
    int gw = (blockIdx.x * 256 + threadIdx.x) >> 5;
    int lane = threadIdx.x & 31;
    if (gw >= 12288) return;
    int i = gw >> 10, r = gw & 1023;
    const float* row = W1 + (long)i * 1048576 + (long)r * 1024 + 512;
    const float* bv = bm + i * 512;
    float s = 0.f;
    for (int o = lane; o < 512; o += 32) s += row[o] * bv[o];
    #pragma unroll
    for (int o = 16; o; o >>= 1) s += __shfl_xor_sync(0xffffffff, s, o);
    if (lane == 0) g_b1f[gw] = b1[i * 1024 + r] + s;
}

// ======================= InstanceNorm1d + ReLU (writes tf32q) ========================
__global__ __launch_bounds__(256) void instnorm_relu()
{
    int bb = blockIdx.x >> 5;
    int gch = blockIdx.x & 31;
    int lane = threadIdx.x & 31, w = threadIdx.x >> 5;
    int c = gch * 32 + lane;
    float* base = g_z + (long)bb * 1048576 + c;
    float s = 0.f;
    for (int n = w; n < 1024; n += 8) s += base[(long)n * 1024];
    __shared__ float sh[8][32];
    sh[w][lane] = s; __syncthreads();
    if (w == 0) { float a = 0; for (int i = 0; i < 8; i++) a += sh[i][lane]; sh[0][lane] = a * (1.f/1024.f); }
    __syncthreads();
    float mean = sh[0][lane];
    __syncthreads();
    float s2 = 0.f;
    for (int n = w; n < 1024; n += 8) { float d = base[(long)n * 1024] - mean; s2 += d * d; }
    sh[w][lane] = s2; __syncthreads();
    if (w == 0) { float a = 0; for (int i = 0; i < 8; i++) a += sh[i][lane];
                  sh[0][lane] = rsqrtf(a * (1.f/1024.f) + 1e-5f); }
    __syncthreads();
    float inv = sh[0][lane];
    for (int n = w; n < 1024; n += 8) {
        long off = (long)n * 1024;
        base[off] = tfq(fmaxf((base[off] - mean) * inv, 0.f));
    }
}

// ======================= elementwise helpers =========================================
__global__ void copy4(float4* __restrict__ dst, const float4* __restrict__ src)
{
    long t = (long)blockIdx.x * 256 + threadIdx.x;
    dst[t] = src[t];
}
__global__ void copy_to_cat(const float4* __restrict__ x)
{
    long t = (long)blockIdx.x * 256 + threadIdx.x;
    long ts = t >> 19, rem = t & 524287;
    long r = rem >> 7, c = rem & 127;
    float4 v = x[ts * 524288 + rem];
    v.x = tfq(v.x); v.y = tfq(v.y); v.z = tfq(v.z); v.w = tfq(v.w);
    ((float4*)g_cat)[ts * 1048576 + r * 256 + c] = v;
}

// ======================= Sinkhorn ====================================================
__global__ void sink_init(const float* __restrict__ bin)
{
    float a = *bin;
    int t = blockIdx.x * 256 + threadIdx.x;
    if (t == 0) g_ctr = 0;
    if (t < 4100) g_ev[t] = 1.f;
    if (t < 8196) {
        int b = t / 2049, r = t - b * 2049;
        float* cb = g_coup + (long)b * 1050625;
        if (r < 1024) cb[(long)r * 1025 + 1024] = a;
        else          cb[(long)1024 * 1025 + (r - 1024)] = a;
    }
}

__global__ __launch_bounds__(256) void sink_prep()
{
    int r = blockIdx.x;
    int b = r / 1025, i = r - b * 1025;
    const float* row = g_coup + (long)b * 1050625 + (long)i * 1025;
    __nv_bfloat16* prow = g_Pb + (long)b * 1050625 + (long)i * 1025;
    int t = threadIdx.x;
    float m = -1e30f;
    for (int j = t; j < 1025; j += 256) m = fmaxf(m, row[j]);
    __shared__ float sm[256];
    sm[t] = m; __syncthreads();
    for (int o = 128; o > 0; o >>= 1) { if (t < o) sm[t] = fmaxf(sm[t], sm[t+o]); __syncthreads(); }
    m = sm[0];
    if (t == 0) g_M[r] = m;
    for (int j = t; j < 1025; j += 256) prow[j] = __float2bfloat16(__expf(row[j] - m));
}

__global__ void transP()
{
    __shared__ __nv_bfloat16 tile[32][33];
    int b = blockIdx.z;
    int x0 = blockIdx.x * 32, y0 = blockIdx.y * 32;
    const __nv_bfloat16* src = g_Pb + (long)b * 1050625;
    __nv_bfloat16* dst = g_PTb + (long)b * 1050625;
    #pragma unroll
    for (int dy = 0; dy < 4; dy++) {
        int row = y0 + threadIdx.y + dy * 8, col = x0 + threadIdx.x;
        if (row < 1025 && col < 1025)
            tile[threadIdx.y + dy * 8][threadIdx.x] = src[(long)row * 1025 + col];
    }
    __syncthreads();
    #pragma unroll
    for (int dy = 0; dy < 4; dy++) {
        int row = x0 + threadIdx.y + dy * 8, col = y0 + threadIdx.x;
        if (row < 1025 && col < 1025)
            dst[(long)row * 1025 + col] = tile[threadIdx.x][threadIdx.y + dy * 8];
    }
}

// persistent: 592 blocks (4 batches x 148), 100 iterations, device-wide barrier
__global__ __launch_bounds__(256) void sink_persist()
{
    const int tid = threadIdx.x, w = tid >> 5, lane = tid & 31;
    const int bb = blockIdx.x / 148, blk = blockIdx.x % 148;
    const int i = blk * 8 + w;
    const bool act = (i < 1025);
    __shared__ float vec[1025];
    const __nv_bfloat16* Pr  = g_Pb  + (long)bb * 1050625 + (long)(act ? i : 0) * 1025;
    const __nv_bfloat16* PTr = g_PTb + (long)bb * 1050625 + (long)(act ? i : 0) * 1025;
    const float mu = (i < 1024) ? (1.f / 2048.f) : 0.5f;
    unsigned target = 0;

    for (int it = 0; it < 100; it++) {
        // ---- row phase: w_i = mu_i / (P_i . ev) ----
        for (int j = tid; j < 1025; j += 256) vec[j] = __ldcg(&g_ev[bb * 1025 + j]);
        __syncthreads();
        if (act) {
            float s = 0.f;
            for (int j = lane; j < 1025; j += 32)
                s += __bfloat162float(Pr[j]) * vec[j];
            #pragma unroll
            for (int o = 16; o; o >>= 1) s += __shfl_xor_sync(0xffffffff, s, o);
            if (lane == 0) g_w[bb * 1025 + i] = mu / s;
        }
        __threadfence();
        __syncthreads();
        target += gridDim.x;
        if (tid == 0) {
            atomicAdd(&g_ctr, 1u);
            while (*((volatile unsigned*)&g_ctr) < target) __nanosleep(64);
        }
        __syncthreads();
        // ---- col phase: ev_j = nu_j / (PT_j . w) ----
        for (int j = tid; j < 1025; j += 256) vec[j] = __ldcg(&g_w[bb * 1025 + j]);
        __syncthreads();
        if (act) {
            float s = 0.f;
            for (int j = lane; j < 1025; j += 32)
                s += __bfloat162float(PTr[j]) * vec[j];
            #pragma unroll
            for (int o = 16; o; o >>= 1) s += __shfl_xor_sync(0xffffffff, s, o);
            if (lane == 0) g_ev[bb * 1025 + i] = mu / s;
        }
        __threadfence();
        __syncthreads();
        target += gridDim.x;
        if (tid == 0) {
            atomicAdd(&g_ctr, 1u);
            while (*((volatile unsigned*)&g_ctr) < target) __nanosleep(64);
        }
        __syncthreads();
    }
}

__global__ void sink_uvfin()
{
    int t = blockIdx.x * 256 + threadIdx.x;
    if (t < 4100) {
        g_u[t]  = logf(g_w[t]) - g_M[t];
        g_vv[t] = logf(g_ev[t]);
    }
}

__global__ void final_out(float* __restrict__ out)
{
    long t = (long)blockIdx.x * 256 + threadIdx.x;
    if (t >= 4202500L) return;
    int b = (int)(t / 1050625);
    int rem = (int)(t - (long)b * 1050625);
    int i = rem / 1025, j = rem - i * 1025;
    out[t] = g_coup[t] + g_u[b * 1025 + i] + g_vv[b * 1025 + j] - NORM_C;
}

// ======================= driver ======================================================
extern "C" void kernel_launch(void* const* d_in, const int* in_sizes, int n_in,
                              void* d_out, int out_size)
{
    (void)in_sizes; (void)n_in; (void)out_size;
    const float* Wq = (const float*)d_in[2];  const float* bq = (const float*)d_in[3];
    const float* Wk = (const float*)d_in[4];  const float* bk = (const float*)d_in[5];
    const float* Wv = (const float*)d_in[6];  const float* bv = (const float*)d_in[7];
    const float* Wm = (const float*)d_in[8];  const float* bm = (const float*)d_in[9];
    const float* W1 = (const float*)d_in[10]; const float* b1 = (const float*)d_in[11];
    const float* W2 = (const float*)d_in[12]; const float* b2 = (const float*)d_in[13];
    const float* Wf = (const float*)d_in[14]; const float* bf = (const float*)d_in[15];
    const float* bin = (const float*)d_in[16];

    cudaFuncSetAttribute(gemm_tc<0>, cudaFuncAttributeMaxDynamicSharedMemorySize, GEMM_SMEM);
    cudaFuncSetAttribute(gemm_tc<1>, cudaFuncAttributeMaxDynamicSharedMemorySize, GEMM_SMEM);
    cudaFuncSetAttribute(flash_attn, cudaFuncAttributeMaxDynamicSharedMemorySize, FLASH_SMEM);

    float *pact, *pcat, *pz, *pmfin, *pcoup, *pwpack, *pbpack, *pwmt, *pW1c, *pb1f, *pW2q, *pWfq;
    cudaGetSymbolAddress((void**)&pact,  g_act);
    cudaGetSymbolAddress((void**)&pcat,  g_cat);
    cudaGetSymbolAddress((void**)&pz,    g_z);
    cudaGetSymbolAddress((void**)&pmfin, g_mfin);
    cudaGetSymbolAddress((void**)&pcoup, g_coup);
    cudaGetSymbolAddress((void**)&pwpack,g_wpack);
    cudaGetSymbolAddress((void**)&pbpack,g_bpack);
    cudaGetSymbolAddress((void**)&pwmt,  g_wmt);
    cudaGetSymbolAddress((void**)&pW1c,  g_W1c);
    cudaGetSymbolAddress((void**)&pb1f,  g_b1f);
    cudaGetSymbolAddress((void**)&pW2q,  g_W2q);
    cudaGetSymbolAddress((void**)&pWfq,  g_Wfq);

    pack_w<<<36864, 256>>>(Wq, Wk, Wv, bq, bk, bv, Wm, W1, W2, Wf);
    fold_b1<<<1536, 256>>>(W1, b1, bm);
    // W1b @ Wm_perm -> g_W1c[:, 512:], batched over 12 layers (A = W1b fp32, QA=1)
    gemm_tc<1><<<dim3(4, 8, 12), 256, GEMM_SMEM>>>(
        W1 + 512, 1024, 1048576, 0, pwmt, 512, 262144, 0, nullptr,
        pW1c + 512, 1024, 1048576, 0, nullptr, 0, 512, 1, 1.f, 0, 1, nullptr, 0);

    float* cur = pact;
    float* nxt = pact + 4194304;
    copy4<<<2048, 256>>>((float4*)cur,             (const float4*)d_in[0]);
    copy4<<<2048, 256>>>((float4*)(cur + 2097152), (const float4*)d_in[1]);
    copy_to_cat<<<4096, 256>>>((const float4*)cur);

    for (int i = 0; i < 12; i++) {
        const int cross = (i & 1);
        gemm_tc<1><<<dim3(12, 32, 2), 256, GEMM_SMEM>>>(
            cur, 512, 2097152, 0, pwpack + (long)i * 786432, 512, 0, 0,
            pbpack + i * 1536, nullptr, 0, 0, 0, nullptr, 0, 512, 1, 1.f, 1, 0,
            nullptr, 0);
        flash_attn<<<dim3(8, 32, 2), 256, FLASH_SMEM>>>(cross);
        // MLP1 on cat=[x_q | mrg_q] with folded weights
        gemm_tc<0><<<dim3(8, 32, 2), 256, GEMM_SMEM>>>(
            pcat, 1024, 4194304, 0, pW1c + (long)i * 1048576, 1024, 0, 0,
            pb1f + i * 1024, pz, 1024, 4194304, 0, nullptr, 0, 1024, 1, 1.f, 0, 0,
            nullptr, 0);
        instnorm_relu<<<256, 256>>>();
        // MLP2 + residual; also writes quantized x into cat[:, :512] for next layer
        gemm_tc<0><<<dim3(4, 32, 2), 256, GEMM_SMEM>>>(
            pz, 1024, 4194304, 0, pW2q + (long)i * 524288, 1024, 0, 0,
            b2 + i * 512, nxt, 512, 2097152, 0, cur, 2097152, 1024, 1, 1.f, 0, 0,
            pcat, 4194304);
        float* tmp = cur; cur = nxt; nxt = tmp;
    }

    gemm_tc<1><<<dim3(4, 32, 2), 256, GEMM_SMEM>>>(
        cur, 512, 2097152, 0, pWfq, 512, 0, 0, bf,
        pmfin, 512, 2097152, 0, nullptr, 0, 512, 1, 1.f, 0, 1, nullptr, 0);
    gemm_tc<0><<<dim3(8, 8, 4), 256, GEMM_SMEM>>>(
        pmfin, 512, 524288, 0, pmfin + 2097152, 512, 524288, 0, nullptr,
        pcoup, 1025, 1050625, 0, nullptr, 0, 512, 1, 0.04419417382415922f, 0, 0,
        nullptr, 0);

    sink_init<<<33, 256>>>(bin);
    sink_prep<<<4100, 256>>>();
    transP<<<dim3(33, 33, 4), dim3(32, 8)>>>();
    sink_persist<<<592, 256>>>();
    sink_uvfin<<<17, 256>>>();
    final_out<<<16417, 256>>>((float*)d_out);
}

// round 6
// speedup vs baseline: 4.8560x; 1.0043x over previous
#include <cuda_runtime.h>
#include <cuda_bf16.h>

// ======================= static scratch =======================
__device__ float g_act[8388608];     // 2 ping-pong [tset][4096,512] fp32 residual stream
__device__ float g_q [4194304];      // [2 tsets][4096, 512] tf32-quantized
__device__ float g_k [4194304];
__device__ float g_v [4194304];
__device__ float g_cat[8388608];     // [2 tsets][4096, 1024]: [:,:512]=x_q, [:,512:]=mrg_q
__device__ float g_z  [8388608];     // [2 tsets][4096, 1024]
__device__ float g_mfin[4194304];    // [2 sets][4096, 512] (tf32q)
__device__ float g_coup[4202500];    // [4,1025,1025]
__device__ __nv_bfloat16 g_Pb [4202500];   // exp(coup - rowmax), bf16
__device__ __nv_bfloat16 g_PTb[4202500];   // transpose of g_Pb
__device__ float g_M [4100];
__device__ float g_w [4100];
__device__ float g_ev[4100];
__device__ float g_u [4100];
__device__ float g_vv[4100];
__device__ unsigned g_ctr4[4];
__device__ float g_wpack[9437184];   // [12][1536][512]  Wq|Wk|Wv (tf32q)
__device__ float g_bpack[18432];     // [12][1536]
__device__ float g_wmt[3145728];     // [12][512(c)][512(o)] = Wm[o][perm(c)] (tf32q)
__device__ float g_W1c[12582912];    // [12][1024][1024]: [:, :512]=W1a_q, [:,512:]=W1b@Wm_q
__device__ float g_b1f[12288];       // [12][1024] = b1 + W1b@bm
__device__ float g_W2q[6291456];     // [12][512][1024]  (tf32q)
__device__ float g_Wfq[262144];      // [512][512]       (tf32q)

#define NORM_C  (-7.6246189861593985f)   // -log(2048)
#define LDS 36
#define GEMM_SMEM  (4*128*LDS*4)                 // old 128x128 kernel (2-stage)
#define GEMM_SMEM5 (3*(256+128)*LDS*4)           // new 256x128 kernel (3-stage) = 165888
#define QPAD 68
#define KPAD 68
#define VPAD 72
#define FLASH_SMEM ((128*QPAD + 64*KPAD + 64*VPAD)*4)

// ======================= tensor-core primitives =======================
__device__ __forceinline__ unsigned f2tf(float x) {
    unsigned u; asm("cvt.rna.tf32.f32 %0, %1;" : "=r"(u) : "f"(x)); return u;
}
__device__ __forceinline__ float tfq(float x) { return __uint_as_float(f2tf(x)); }
__device__ __forceinline__ void mma8(float* d, const unsigned* a, const unsigned* b) {
    asm volatile(
        "mma.sync.aligned.m16n8k8.row.col.f32.tf32.tf32.f32 "
        "{%0,%1,%2,%3}, {%4,%5,%6,%7}, {%8,%9}, {%0,%1,%2,%3};\n"
        : "+f"(d[0]), "+f"(d[1]), "+f"(d[2]), "+f"(d[3])
        : "r"(a[0]), "r"(a[1]), "r"(a[2]), "r"(a[3]), "r"(b[0]), "r"(b[1]));
}
__device__ __forceinline__ void cpa16(float* s, const float* g) {
    unsigned sa = (unsigned)__cvta_generic_to_shared(s);
    asm volatile("cp.async.ca.shared.global [%0], [%1], 16;\n" :: "r"(sa), "l"(g));
}
#define LDSM4(d0,d1,d2,d3,addr) \
    asm volatile("ldmatrix.sync.aligned.m8n8.x4.shared.b16 {%0,%1,%2,%3}, [%4];\n" \
        : "=r"(d0), "=r"(d1), "=r"(d2), "=r"(d3) : "r"(addr))

// ======================= gemm512: 256x128 tile, 512 thr, 3-stage, 1 sync/kt ==========
template <int QA>
__global__ __launch_bounds__(512, 1) void gemm512(
    const float* __restrict__ A, int lda, long aS1,
    const float* __restrict__ B, int ldb,
    const float* __restrict__ bias,
    float* __restrict__ C, int ldc, long cS1,
    const float* __restrict__ resid, long rS1,
    int K, float alpha, int qkv_mode, int quantO,
    float* __restrict__ Cq, long cqS1)
{
    extern __shared__ float smem[];
    const int z = blockIdx.z;
    A += z * aS1;
    C += z * cS1;
    if (resid) resid += z * rS1;
    if (Cq)    Cq    += z * cqS1;
    const int tid = threadIdx.x;
    const int bm = blockIdx.y * 256, bn = blockIdx.x * 128;
    const int KT = K >> 5;

    auto issue = [&](int kt, int st) {
        const float* Ag = A + (long)bm * lda + kt * 32;
        float* as = smem + st * 256 * LDS;
        #pragma unroll
        for (int i = 0; i < 4; i++) {
            int idx = tid + i * 512, r = idx >> 3, c = (idx & 7) * 4;
            cpa16(as + r * LDS + c, Ag + (long)r * lda + c);
        }
        const float* Bg = B + (long)bn * ldb + kt * 32;
        float* bs = smem + 3 * 256 * LDS + st * 128 * LDS;
        #pragma unroll
        for (int i = 0; i < 2; i++) {
            int idx = tid + i * 512, r = idx >> 3, c = (idx & 7) * 4;
            cpa16(bs + r * LDS + c, Bg + (long)r * ldb + c);
        }
        asm volatile("cp.async.commit_group;\n");
    };

    float acc[4][4][4] = {};
    const int wid = tid >> 5, lane = tid & 31;
    const int wm = wid & 3, wn = wid >> 2, g = lane >> 2, q = lane & 3;
    const int t4 = lane >> 3, tr8 = lane & 7;
    const unsigned smem_u = (unsigned)__cvta_generic_to_shared(smem);
    unsigned a_off[4], b_off[2];
    #pragma unroll
    for (int mt = 0; mt < 4; mt++)
        a_off[mt] = smem_u + (((wm * 64 + mt * 16 + ((t4 & 1) << 3) + tr8) * LDS
                              + ((t4 >> 1) << 2)) << 2);
    #pragma unroll
    for (int p = 0; p < 2; p++)
        b_off[p] = smem_u + ((3 * 256 * LDS
                              + (wn * 32 + p * 16 + ((t4 >> 1) << 3) + tr8) * LDS
                              + ((t4 & 1) << 2)) << 2);

    issue(0, 0);
    issue(1, 1);
    for (int kt = 0; kt < KT; kt++) {
        const int st = kt % 3;
        if (kt + 1 < KT) asm volatile("cp.async.wait_group 1;\n");
        else             asm volatile("cp.async.wait_group 0;\n");
        __syncthreads();
        const unsigned sbA = st * (256 * LDS * 4);
        const unsigned sbB = st * (128 * LDS * 4);
        #pragma unroll
        for (int k8 = 0; k8 < 4; k8++) {
            unsigned af[4][4], bf[4][2];
            #pragma unroll
            for (int mt = 0; mt < 4; mt++) {
                LDSM4(af[mt][0], af[mt][1], af[mt][2], af[mt][3],
                      a_off[mt] + sbA + k8 * 32);
                if (QA) {
                    #pragma unroll
                    for (int e = 0; e < 4; e++)
                        af[mt][e] = f2tf(__uint_as_float(af[mt][e]));
                }
            }
            #pragma unroll
            for (int p = 0; p < 2; p++)
                LDSM4(bf[2*p][0], bf[2*p][1], bf[2*p+1][0], bf[2*p+1][1],
                      b_off[p] + sbB + k8 * 32);
            #pragma unroll
            for (int mt = 0; mt < 4; mt++)
                #pragma unroll
                for (int nt = 0; nt < 4; nt++) mma8(acc[mt][nt], af[mt], bf[nt]);
        }
        if (kt + 2 < KT) issue(kt + 2, (kt + 2) % 3);
    }

    const long zoff = (long)z * 2097152;
    #pragma unroll
    for (int mt = 0; mt < 4; mt++)
        #pragma unroll
        for (int nt = 0; nt < 4; nt++) {
            int r0 = bm + wm * 64 + mt * 16 + g;
            int c0 = bn + wn * 32 + nt * 8 + q * 2;
            #pragma unroll
            for (int i2 = 0; i2 < 2; i2++) {
                int r = r0 + i2 * 8;
                #pragma unroll
                for (int j2 = 0; j2 < 2; j2++) {
                    int c = c0 + j2;
                    float v = alpha * acc[mt][nt][i2 * 2 + j2];
                    if (bias) v += bias[c];
                    if (qkv_mode) {
                        float vq = tfq(v);
                        if (c < 512)       g_q[zoff + (long)r * 512 + c] = vq;
                        else if (c < 1024) g_k[zoff + (long)r * 512 + (c - 512)] = vq;
                        else               g_v[zoff + (long)r * 512 + (c - 1024)] = vq;
                    } else {
                        if (resid) v += resid[(long)r * ldc + c];
                        if (quantO) v = tfq(v);
                        C[(long)r * ldc + c] = v;
                        if (Cq) Cq[(long)r * 1024 + c] = tfq(v);
                    }
                }
            }
        }
}

// ======================= old 128x128 kernel (small-M GEMMs) ==========================
template <int QA>
__global__ __launch_bounds__(256, 2) void gemm_tc(
    const float* __restrict__ A, int lda, long aS1, long aS2,
    const float* __restrict__ B, int ldb, long bS1, long bS2,
    const float* __restrict__ bias,
    float* __restrict__ C, int ldc, long cS1, long cS2,
    int K, int zmod, float alpha, int quantO)
{
    extern __shared__ float smem[];
    float* As = smem;
    const int z = blockIdx.z, z1 = z / zmod, z2 = z - z1 * zmod;
    A += z1 * aS1 + z2 * aS2;
    B += z1 * bS1 + z2 * bS2;
    C += z1 * cS1 + z2 * cS2;
    const int tid = threadIdx.x;
    const int bm = blockIdx.y * 128, bn = blockIdx.x * 128;
    const int KT = K >> 5;

    auto issue = [&](int kt, int st) {
        const float* Ag = A + (long)bm * lda + kt * 32;
        float* as = As + st * 128 * LDS;
        #pragma unroll
        for (int i = 0; i < 4; i++) {
            int idx = tid + i * 256, r = idx >> 3, c = (idx & 7) * 4;
            cpa16(as + r * LDS + c, Ag + (long)r * lda + c);
        }
        const float* Bg = B + (long)bn * ldb + kt * 32;
        float* bs = As + 2 * 128 * LDS + st * 128 * LDS;
        #pragma unroll
        for (int i = 0; i < 4; i++) {
            int idx = tid + i * 256, r = idx >> 3, c = (idx & 7) * 4;
            cpa16(bs + r * LDS + c, Bg + (long)r * ldb + c);
        }
        asm volatile("cp.async.commit_group;\n");
    };

    float acc[4][4][4] = {};
    const int wid = tid >> 5, lane = tid & 31;
    const int wm = wid & 1, wn = wid >> 1, g = lane >> 2, q = lane & 3;
    const int t4 = lane >> 3, tr8 = lane & 7;
    const unsigned smem_u = (unsigned)__cvta_generic_to_shared(smem);
    unsigned a_off[4], b_off[2];
    #pragma unroll
    for (int mt = 0; mt < 4; mt++)
        a_off[mt] = smem_u + (((wm * 64 + mt * 16 + ((t4 & 1) << 3) + tr8) * LDS
                              + ((t4 >> 1) << 2)) << 2);
    #pragma unroll
    for (int p = 0; p < 2; p++)
        b_off[p] = smem_u + ((2 * 128 * LDS
                              + (wn * 32 + p * 16 + ((t4 >> 1) << 3) + tr8) * LDS
                              + ((t4 & 1) << 2)) << 2);

    issue(0, 0);
    for (int kt = 0; kt < KT; kt++) {
        int st = kt & 1;
        if (kt + 1 < KT) { issue(kt + 1, st ^ 1); asm volatile("cp.async.wait_group 1;\n"); }
        else             { asm volatile("cp.async.wait_group 0;\n"); }
        __syncthreads();
        const unsigned sb = st * (128 * LDS * 4);
        #pragma unroll
        for (int k8 = 0; k8 < 4; k8++) {
            unsigned af[4][4], bf[4][2];
            #pragma unroll
            for (int mt = 0; mt < 4; mt++) {
                LDSM4(af[mt][0], af[mt][1], af[mt][2], af[mt][3],
                      a_off[mt] + sb + k8 * 32);
                if (QA) {
                    #pragma unroll
                    for (int e = 0; e < 4; e++)
                        af[mt][e] = f2tf(__uint_as_float(af[mt][e]));
                }
            }
            #pragma unroll
            for (int p = 0; p < 2; p++)
                LDSM4(bf[2*p][0], bf[2*p][1], bf[2*p+1][0], bf[2*p+1][1],
                      b_off[p] + sb + k8 * 32);
            #pragma unroll
            for (int mt = 0; mt < 4; mt++)
                #pragma unroll
                for (int nt = 0; nt < 4; nt++) mma8(acc[mt][nt], af[mt], bf[nt]);
        }
        __syncthreads();
    }

    #pragma unroll
    for (int mt = 0; mt < 4; mt++)
        #pragma unroll
        for (int nt = 0; nt < 4; nt++) {
            int r0 = bm + wm * 64 + mt * 16 + g;
            int c0 = bn + wn * 32 + nt * 8 + q * 2;
            #pragma unroll
            for (int i2 = 0; i2 < 2; i2++) {
                int r = r0 + i2 * 8;
                #pragma unroll
                for (int j2 = 0; j2 < 2; j2++) {
                    int c = c0 + j2;
                    float v = alpha * acc[mt][nt][i2 * 2 + j2];
                    if (bias) v += bias[c];
                    if (quantO) v = tfq(v);
                    C[(long)r * ldc + c] = v;
                }
            }
        }
}

// ======================= fused flash attention (writes into g_cat msg half) ==========
__global__ __launch_bounds__(256, 2) void flash_attn(int cross)
{
    extern __shared__ float smem[];
    float* Qs = smem;
    float* Ks = smem + 128 * QPAD;
    float* Vs = Ks + 64 * KPAD;
    const int ts = blockIdx.z;
    const int os = cross ? (1 - ts) : ts;
    const int bh = blockIdx.y, b = bh >> 3, h = bh & 7;
    const int m0 = blockIdx.x * 128;
    const int tid = threadIdx.x, wid = tid >> 5, lane = tid & 31;
    const int g = lane >> 2, q = lane & 3;
    const int t4 = lane >> 3, tr8 = lane & 7;

    const float* Qg = g_q + (long)ts * 2097152 + (long)(b * 1024 + m0) * 512 + h * 64;
    const float* Kg = g_k + (long)os * 2097152 + (long)(b * 1024) * 512 + h * 64;
    const float* Vg = g_v + (long)os * 2097152 + (long)(b * 1024) * 512 + h * 64;

    #pragma unroll
    for (int i = 0; i < 8; i++) {
        int idx = tid + i * 256, r = idx >> 4, c = (idx & 15) * 4;
        cpa16(Qs + r * QPAD + c, Qg + (long)r * 512 + c);
    }
    asm volatile("cp.async.commit_group;\n");

    auto loadKV = [&](int t) {
        #pragma unroll
        for (int i = 0; i < 4; i++) {
            int idx = tid + i * 256, r = idx >> 4, c = (idx & 15) * 4;
            cpa16(Ks + r * KPAD + c, Kg + (long)(t * 64 + r) * 512 + c);
        }
        #pragma unroll
        for (int i = 0; i < 4; i++) {
            int idx = tid + i * 256, r = idx >> 4, c = (idx & 15) * 4;
            cpa16(Vs + r * VPAD + c, Vg + (long)(t * 64 + r) * 512 + c);
        }
        asm volatile("cp.async.commit_group;\n");
    };
    loadKV(0);

    const int wr = wid * 16;
    const unsigned smem_u = (unsigned)__cvta_generic_to_shared(smem);
    const unsigned aq_off = smem_u + (((wr + ((t4 & 1) << 3) + tr8) * QPAD
                                      + ((t4 >> 1) << 2)) << 2);
    unsigned bk_off[4];
    #pragma unroll
    for (int p = 0; p < 4; p++)
        bk_off[p] = smem_u + ((128 * QPAD
                               + (p * 16 + ((t4 >> 1) << 3) + tr8) * KPAD
                               + ((t4 & 1) << 2)) << 2);

    float mp0 = -1e30f, mp1 = -1e30f, l0 = 0.f, l1 = 0.f;
    float o[8][4] = {};

    for (int t = 0; t < 16; t++) {
        asm volatile("cp.async.wait_group 0;\n");
        __syncthreads();
        float s[8][4] = {};
        #pragma unroll
        for (int j = 0; j < 8; j++) {
            unsigned aq[4];
            LDSM4(aq[0], aq[1], aq[2], aq[3], aq_off + j * 32);
            #pragma unroll
            for (int p = 0; p < 4; p++) {
                unsigned bk0[2], bk1[2];
                LDSM4(bk0[0], bk0[1], bk1[0], bk1[1], bk_off[p] + j * 32);
                mma8(s[2*p],   aq, bk0);
                mma8(s[2*p+1], aq, bk1);
            }
        }
        float lm0 = -1e30f, lm1 = -1e30f;
        #pragma unroll
        for (int nt = 0; nt < 8; nt++) {
            #pragma unroll
            for (int e = 0; e < 4; e++) s[nt][e] *= 0.125f;
            lm0 = fmaxf(lm0, fmaxf(s[nt][0], s[nt][1]));
            lm1 = fmaxf(lm1, fmaxf(s[nt][2], s[nt][3]));
        }
        lm0 = fmaxf(lm0, __shfl_xor_sync(0xffffffff, lm0, 1));
        lm0 = fmaxf(lm0, __shfl_xor_sync(0xffffffff, lm0, 2));
        lm1 = fmaxf(lm1, __shfl_xor_sync(0xffffffff, lm1, 1));
        lm1 = fmaxf(lm1, __shfl_xor_sync(0xffffffff, lm1, 2));
        float mn0 = fmaxf(mp0, lm0), mn1 = fmaxf(mp1, lm1);
        float a0 = __expf(mp0 - mn0), a1 = __expf(mp1 - mn1);
        float ps0 = 0.f, ps1 = 0.f;
        #pragma unroll
        for (int nt = 0; nt < 8; nt++) {
            s[nt][0] = __expf(s[nt][0] - mn0);
            s[nt][1] = __expf(s[nt][1] - mn0);
            s[nt][2] = __expf(s[nt][2] - mn1);
            s[nt][3] = __expf(s[nt][3] - mn1);
            ps0 += s[nt][0] + s[nt][1];
            ps1 += s[nt][2] + s[nt][3];
        }
        ps0 += __shfl_xor_sync(0xffffffff, ps0, 1);
        ps0 += __shfl_xor_sync(0xffffffff, ps0, 2);
        ps1 += __shfl_xor_sync(0xffffffff, ps1, 1);
        ps1 += __shfl_xor_sync(0xffffffff, ps1, 2);
        l0 = l0 * a0 + ps0;  l1 = l1 * a1 + ps1;
        mp0 = mn0;  mp1 = mn1;
        #pragma unroll
        for (int tt = 0; tt < 8; tt++) {
            o[tt][0] *= a0; o[tt][1] *= a0; o[tt][2] *= a1; o[tt][3] *= a1;
        }
        const int srcA = (lane & ~3) | (q >> 1);
        const int srcB = srcA + 2;
        const bool odd = q & 1;
        #pragma unroll
        for (int j = 0; j < 8; j++) {
            float v00 = __shfl_sync(0xffffffff, s[j][0], srcA);
            float v01 = __shfl_sync(0xffffffff, s[j][1], srcA);
            float v10 = __shfl_sync(0xffffffff, s[j][2], srcA);
            float v11 = __shfl_sync(0xffffffff, s[j][3], srcA);
            float w00 = __shfl_sync(0xffffffff, s[j][0], srcB);
            float w01 = __shfl_sync(0xffffffff, s[j][1], srcB);
            float w10 = __shfl_sync(0xffffffff, s[j][2], srcB);
            float w11 = __shfl_sync(0xffffffff, s[j][3], srcB);
            unsigned ap[4];
            ap[0] = f2tf(odd ? v01 : v00);
            ap[1] = f2tf(odd ? v11 : v10);
            ap[2] = f2tf(odd ? w01 : w00);
            ap[3] = f2tf(odd ? w11 : w10);
            #pragma unroll
            for (int tt = 0; tt < 8; tt++) {
                unsigned bv[2];
                bv[0] = __float_as_uint(Vs[(j * 8 + q) * VPAD + tt * 8 + g]);
                bv[1] = __float_as_uint(Vs[(j * 8 + q + 4) * VPAD + tt * 8 + g]);
                mma8(o[tt], ap, bv);
            }
        }
        __syncthreads();
        if (t < 15) loadKV(t + 1);
    }

    float inv0 = 1.f / l0, inv1 = 1.f / l1;
    float* Og = g_cat + (long)ts * 4194304
              + (long)(b * 1024 + m0 + wr) * 1024 + 512 + h * 64;
    #pragma unroll
    for (int tt = 0; tt < 8; tt++) {
        int c = tt * 8 + q * 2;
        Og[(long)g * 1024 + c]           = tfq(o[tt][0] * inv0);
        Og[(long)g * 1024 + c + 1]       = tfq(o[tt][1] * inv0);
        Og[(long)(g + 8) * 1024 + c]     = tfq(o[tt][2] * inv1);
        Og[(long)(g + 8) * 1024 + c + 1] = tfq(o[tt][3] * inv1);
    }
}

// ======================= weight pack / quantize ======================================
__global__ void pack_w(const float* __restrict__ Wq, const float* __restrict__ Wk,
                       const float* __restrict__ Wv, const float* __restrict__ bq,
                       const float* __restrict__ bk, const float* __restrict__ bv,
                       const float* __restrict__ Wm, const float* __restrict__ W1,
                       const float* __restrict__ W2, const float* __restrict__ Wf)
{
    long t = (long)blockIdx.x * 256 + threadIdx.x;
    if (t < 9437184) {
        long i = t / 786432; long rem = t - i * 786432;
        int row = (int)(rem >> 9), d = (int)(rem & 511);
        const float* src = row < 512 ? Wq : (row < 1024 ? Wk : Wv);
        g_wpack[t] = tfq(src[i * 262144 + (long)(row & 511) * 512 + d]);
    }
    if (t < 18432) {
        long i = t / 1536; int row = (int)(t - i * 1536);
        const float* sb = row < 512 ? bq : (row < 1024 ? bk : bv);
        g_bpack[t] = sb[i * 512 + (row & 511)];
    }
    if (t < 3145728) {
        long i = t >> 18; long rem = t & 262143;
        int c = (int)(rem >> 9), o = (int)(rem & 511);
        int s = (c & 63) * 8 + (c >> 6);
        g_wmt[t] = tfq(Wm[i * 262144 + (long)o * 512 + s]);
    }
    if (t < 6291456) {
        long i = t / 524288; long rem = t - i * 524288;
        int r = (int)(rem >> 9), c = (int)(rem & 511);
        g_W1c[i * 1048576 + (long)r * 1024 + c] = tfq(W1[i * 1048576 + (long)r * 1024 + c]);
    }
    if (t < 6291456)  g_W2q[t] = tfq(W2[t]);
    if (t < 262144)   g_Wfq[t] = tfq(Wf[t]);
}

__global__ void fold_b1(const float* __restrict__ W1, const float* __restrict__ b1,
                        const float* __restrict__ bm)
{
    int gw = (blockIdx.x * 256 + threadIdx.x) >> 5;
    int lane = threadIdx.x & 31;
    if (gw >= 12288) return;
    int i = gw >> 10, r = gw & 1023;
    const float* row = W1 + (long)i * 1048576 + (long)r * 1024 + 512;
    const float* bv = bm + i * 512;
    float s = 0.f;
    for (int o = lane; o < 512; o += 32) s += row[o] * bv[o];
    #pragma unroll
    for (int o = 16; o; o >>= 1) s += __shfl_xor_sync(0xffffffff, s, o);
    if (lane == 0) g_b1f[gw] = b1[i * 1024 + r] + s;
}

// ======================= InstanceNorm1d + ReLU, 2-pass (sum+sumsq fused) ============
__global__ __launch_bounds__(256) void instnorm_relu()
{
    int bb = blockIdx.x >> 5;
    int gch = blockIdx.x & 31;
    int lane = threadIdx.x & 31, w = threadIdx.x >> 5;
    int c = gch * 32 + lane;
    float* base = g_z + (long)bb * 1048576 + c;
    float s = 0.f, s2 = 0.f;
    for (int n = w; n < 1024; n += 8) {
        float x = base[(long)n * 1024];
        s += x; s2 = fmaf(x, x, s2);
    }
    __shared__ float sh[8][32], sh2[8][32];
    sh[w][lane] = s; sh2[w][lane] = s2; __syncthreads();
    if (w == 0) {
        float a = 0, a2 = 0;
        #pragma unroll
        for (int i = 0; i < 8; i++) { a += sh[i][lane]; a2 += sh2[i][lane]; }
        float mean = a * (1.f / 1024.f);
        float var = a2 * (1.f / 1024.f) - mean * mean;
        sh[0][lane] = mean;
        sh2[0][lane] = rsqrtf(var + 1e-5f);
    }
    __syncthreads();
    float mean = sh[0][lane], inv = sh2[0][lane];
    for (int n = w; n < 1024; n += 8) {
        long off = (long)n * 1024;
        base[off] = tfq(fmaxf((base[off] - mean) * inv, 0.f));
    }
}

// ======================= elementwise helpers =========================================
__global__ void copy4(float4* __restrict__ dst, const float4* __restrict__ src)
{
    long t = (long)blockIdx.x * 256 + threadIdx.x;
    dst[t] = src[t];
}
__global__ void copy_to_cat(const float4* __restrict__ x)
{
    long t = (long)blockIdx.x * 256 + threadIdx.x;
    long ts = t >> 19, rem = t & 524287;
    long r = rem >> 7, c = rem & 127;
    float4 v = x[ts * 524288 + rem];
    v.x = tfq(v.x); v.y = tfq(v.y); v.z = tfq(v.z); v.w = tfq(v.w);
    ((float4*)g_cat)[ts * 1048576 + r * 256 + c] = v;
}

// ======================= Sinkhorn ====================================================
__global__ void sink_init(const float* __restrict__ bin)
{
    float a = *bin;
    int t = blockIdx.x * 256 + threadIdx.x;
    if (t < 4) g_ctr4[t] = 0;
    if (t < 4100) g_ev[t] = 1.f;
    if (t < 8196) {
        int b = t / 2049, r = t - b * 2049;
        float* cb = g_coup + (long)b * 1050625;
        if (r < 1024) cb[(long)r * 1025 + 1024] = a;
        else          cb[(long)1024 * 1025 + (r - 1024)] = a;
    }
}

__global__ __launch_bounds__(256) void sink_prep()
{
    int r = blockIdx.x;
    int b = r / 1025, i = r - b * 1025;
    const float* row = g_coup + (long)b * 1050625 + (long)i * 1025;
    __nv_bfloat16* prow = g_Pb + (long)b * 1050625 + (long)i * 1025;
    int t = threadIdx.x;
    float m = -1e30f;
    for (int j = t; j < 1025; j += 256) m = fmaxf(m, row[j]);
    __shared__ float sm[256];
    sm[t] = m; __syncthreads();
    for (int o = 128; o > 0; o >>= 1) { if (t < o) sm[t] = fmaxf(sm[t], sm[t+o]); __syncthreads(); }
    m = sm[0];
    if (t == 0) g_M[r] = m;
    for (int j = t; j < 1025; j += 256) prow[j] = __float2bfloat16(__expf(row[j] - m));
}

__global__ void transP()
{
    __shared__ __nv_bfloat16 tile[32][33];
    int b = blockIdx.z;
    int x0 = blockIdx.x * 32, y0 = blockIdx.y * 32;
    const __nv_bfloat16* src = g_Pb + (long)b * 1050625;
    __nv_bfloat16* dst = g_PTb + (long)b * 1050625;
    #pragma unroll
    for (int dy = 0; dy < 4; dy++) {
        int row = y0 + threadIdx.y + dy * 8, col = x0 + threadIdx.x;
        if (row < 1025 && col < 1025)
            tile[threadIdx.y + dy * 8][threadIdx.x] = src[(long)row * 1025 + col];
    }
    __syncthreads();
    #pragma unroll
    for (int dy = 0; dy < 4; dy++) {
        int row = x0 + threadIdx.y + dy * 8, col = y0 + threadIdx.x;
        if (row < 1025 && col < 1025)
            dst[(long)row * 1025 + col] = tile[threadIdx.x][threadIdx.y + dy * 8];
    }
}

// persistent with PER-BATCH barriers: 4 x 148 blocks
__global__ __launch_bounds__(256) void sink_persist()
{
    const int tid = threadIdx.x, w = tid >> 5, lane = tid & 31;
    const int bb = blockIdx.x / 148, blk = blockIdx.x % 148;
    const int i = blk * 8 + w;
    const bool act = (i < 1025);
    __shared__ float vec[1025];
    const __nv_bfloat16* Pr  = g_Pb  + (long)bb * 1050625 + (long)(act ? i : 0) * 1025;
    const __nv_bfloat16* PTr = g_PTb + (long)bb * 1050625 + (long)(act ? i : 0) * 1025;
    const float mu = (i < 1024) ? (1.f / 2048.f) : 0.5f;
    unsigned target = 0;
    volatile unsigned* ctr = &g_ctr4[bb];

    for (int it = 0; it < 100; it++) {
        for (int j = tid; j < 1025; j += 256) vec[j] = __ldcg(&g_ev[bb * 1025 + j]);
        __syncthreads();
        if (act) {
            float s = 0.f;
            for (int j = lane; j < 1025; j += 32)
                s += __bfloat162float(Pr[j]) * vec[j];
            #pragma unroll
            for (int o = 16; o; o >>= 1) s += __shfl_xor_sync(0xffffffff, s, o);
            if (lane == 0) g_w[bb * 1025 + i] = mu / s;
        }
        __threadfence();
        __syncthreads();
        target += 148;
        if (tid == 0) {
            atomicAdd(&g_ctr4[bb], 1u);
            while (*ctr < target) __nanosleep(64);
        }
        __syncthreads();
        for (int j = tid; j < 1025; j += 256) vec[j] = __ldcg(&g_w[bb * 1025 + j]);
        __syncthreads();
        if (act) {
            float s = 0.f;
            for (int j = lane; j < 1025; j += 32)
                s += __bfloat162float(PTr[j]) * vec[j];
            #pragma unroll
            for (int o = 16; o; o >>= 1) s += __shfl_xor_sync(0xffffffff, s, o);
            if (lane == 0) g_ev[bb * 1025 + i] = mu / s;
        }
        __threadfence();
        __syncthreads();
        target += 148;
        if (tid == 0) {
            atomicAdd(&g_ctr4[bb], 1u);
            while (*ctr < target) __nanosleep(64);
        }
        __syncthreads();
    }
}

__global__ void sink_uvfin()
{
    int t = blockIdx.x * 256 + threadIdx.x;
    if (t < 4100) {
        g_u[t]  = logf(g_w[t]) - g_M[t];
        g_vv[t] = logf(g_ev[t]);
    }
}

__global__ void final_out(float* __restrict__ out)
{
    long t = (long)blockIdx.x * 256 + threadIdx.x;
    if (t >= 4202500L) return;
    int b = (int)(t / 1050625);
    int rem = (int)(t - (long)b * 1050625);
    int i = rem / 1025, j = rem - i * 1025;
    out[t] = g_coup[t] + g_u[b * 1025 + i] + g_vv[b * 1025 + j] - NORM_C;
}

// ======================= driver ======================================================
extern "C" void kernel_launch(void* const* d_in, const int* in_sizes, int n_in,
                              void* d_out, int out_size)
{
    (void)in_sizes; (void)n_in; (void)out_size;
    const float* Wq = (const float*)d_in[2];  const float* bq = (const float*)d_in[3];
    const float* Wk = (const float*)d_in[4];  const float* bk = (const float*)d_in[5];
    const float* Wv = (const float*)d_in[6];  const float* bv = (const float*)d_in[7];
    const float* Wm = (const float*)d_in[8];  const float* bm = (const float*)d_in[9];
    const float* W1 = (const float*)d_in[10]; const float* b1 = (const float*)d_in[11];
    const float* W2 = (const float*)d_in[12]; const float* b2 = (const float*)d_in[13];
    const float* Wf = (const float*)d_in[14]; const float* bf = (const float*)d_in[15];
    const float* bin = (const float*)d_in[16];

    cudaFuncSetAttribute(gemm_tc<0>,  cudaFuncAttributeMaxDynamicSharedMemorySize, GEMM_SMEM);
    cudaFuncSetAttribute(gemm_tc<1>,  cudaFuncAttributeMaxDynamicSharedMemorySize, GEMM_SMEM);
    cudaFuncSetAttribute(gemm512<0>,  cudaFuncAttributeMaxDynamicSharedMemorySize, GEMM_SMEM5);
    cudaFuncSetAttribute(gemm512<1>,  cudaFuncAttributeMaxDynamicSharedMemorySize, GEMM_SMEM5);
    cudaFuncSetAttribute(flash_attn,  cudaFuncAttributeMaxDynamicSharedMemorySize, FLASH_SMEM);

    float *pact, *pcat, *pz, *pmfin, *pcoup, *pwpack, *pbpack, *pwmt, *pW1c, *pb1f, *pW2q, *pWfq;
    cudaGetSymbolAddress((void**)&pact,  g_act);
    cudaGetSymbolAddress((void**)&pcat,  g_cat);
    cudaGetSymbolAddress((void**)&pz,    g_z);
    cudaGetSymbolAddress((void**)&pmfin, g_mfin);
    cudaGetSymbolAddress((void**)&pcoup, g_coup);
    cudaGetSymbolAddress((void**)&pwpack,g_wpack);
    cudaGetSymbolAddress((void**)&pbpack,g_bpack);
    cudaGetSymbolAddress((void**)&pwmt,  g_wmt);
    cudaGetSymbolAddress((void**)&pW1c,  g_W1c);
    cudaGetSymbolAddress((void**)&pb1f,  g_b1f);
    cudaGetSymbolAddress((void**)&pW2q,  g_W2q);
    cudaGetSymbolAddress((void**)&pWfq,  g_Wfq);

    pack_w<<<36864, 256>>>(Wq, Wk, Wv, bq, bk, bv, Wm, W1, W2, Wf);
    fold_b1<<<1536, 256>>>(W1, b1, bm);
    gemm_tc<1><<<dim3(4, 8, 12), 256, GEMM_SMEM>>>(
        W1 + 512, 1024, 1048576, 0, pwmt, 512, 262144, 0, nullptr,
        pW1c + 512, 1024, 1048576, 0, 512, 1, 1.f, 1);

    float* cur = pact;
    float* nxt = pact + 4194304;
    copy4<<<2048, 256>>>((float4*)cur,             (const float4*)d_in[0]);
    copy4<<<2048, 256>>>((float4*)(cur + 2097152), (const float4*)d_in[1]);
    copy_to_cat<<<4096, 256>>>((const float4*)cur);

    for (int i = 0; i < 12; i++) {
        const int cross = (i & 1);
        gemm512<1><<<dim3(12, 16, 2), 512, GEMM_SMEM5>>>(
            cur, 512, 2097152, pwpack + (long)i * 786432, 512,
            pbpack + i * 1536, nullptr, 0, 0, nullptr, 0, 512, 1.f, 1, 0, nullptr, 0);
        flash_attn<<<dim3(8, 32, 2), 256, FLASH_SMEM>>>(cross);
        gemm512<0><<<dim3(8, 16, 2), 512, GEMM_SMEM5>>>(
            pcat, 1024, 4194304, pW1c + (long)i * 1048576, 1024,
            pb1f + i * 1024, pz, 1024, 4194304, nullptr, 0, 1024, 1.f, 0, 0, nullptr, 0);
        instnorm_relu<<<256, 256>>>();
        gemm512<0><<<dim3(4, 16, 2), 512, GEMM_SMEM5>>>(
            pz, 1024, 4194304, pW2q + (long)i * 524288, 1024,
            b2 + i * 512, nxt, 512, 2097152, cur, 2097152, 1024, 1.f, 0, 0,
            pcat, 4194304);
        float* tmp = cur; cur = nxt; nxt = tmp;
    }

    gemm512<1><<<dim3(4, 16, 2), 512, GEMM_SMEM5>>>(
        cur, 512, 2097152, pWfq, 512, bf,
        pmfin, 512, 2097152, nullptr, 0, 512, 1.f, 0, 1, nullptr, 0);
    gemm_tc<0><<<dim3(8, 8, 4), 256, GEMM_SMEM>>>(
        pmfin, 512, 524288, 0, pmfin + 2097152, 512, 524288, 0, nullptr,
        pcoup, 1025, 1050625, 0, 512, 1, 0.04419417382415922f, 0);

    sink_init<<<33, 256>>>(bin);
    sink_prep<<<4100, 256>>>();
    transP<<<dim3(33, 33, 4), dim3(32, 8)>>>();
    sink_persist<<<592, 256>>>();
    sink_uvfin<<<17, 256>>>();
    final_out<<<16417, 256>>>((float*)d_out);
}